// round 1
// baseline (speedup 1.0000x reference)
#include <cuda_runtime.h>

#define N_NODES 100000
#define N_EDGES 1600000

// ---------------- scratch (device globals; no runtime allocation) ----------
__device__ float g_deg [N_NODES];
__device__ float g_dinv[N_NODES];
__device__ float g_wn  [N_EDGES];
__device__ float g_bufA[(size_t)N_NODES * 128];
__device__ float g_bufB[(size_t)N_NODES * 128];
__device__ float g_bufC[(size_t)N_NODES * 128];
__device__ float g_acc [(size_t)N_NODES * 64];
__device__ float g_h   [(size_t)N_NODES * 64];

// ---------------- elementwise helpers --------------------------------------
__global__ void k_zero4(float4* __restrict__ p, int n4) {
    int i = blockIdx.x * blockDim.x + threadIdx.x;
    if (i < n4) p[i] = make_float4(0.f, 0.f, 0.f, 0.f);
}

__global__ void k_neg4(const float4* __restrict__ a, float4* __restrict__ o, int n4) {
    int i = blockIdx.x * blockDim.x + threadIdx.x;
    if (i < n4) {
        float4 v = a[i];
        o[i] = make_float4(-v.x, -v.y, -v.z, -v.w);
    }
}

// ---------------- graph normalization ---------------------------------------
__global__ void k_deg(const int* __restrict__ dst, float* __restrict__ deg) {
    int e = blockIdx.x * blockDim.x + threadIdx.x;
    if (e < N_EDGES) atomicAdd(&deg[dst[e]], 1.0f);
}

__global__ void k_dinv(const float* __restrict__ deg, float* __restrict__ dinv) {
    int i = blockIdx.x * blockDim.x + threadIdx.x;
    if (i < N_NODES) {
        float d = deg[i];
        dinv[i] = (d > 0.f) ? rsqrtf(fmaxf(d, 1.f)) : 0.f;
    }
}

__global__ void k_wnorm(const int* __restrict__ src, const int* __restrict__ dst,
                        const float* __restrict__ dinv, float* __restrict__ wn) {
    int e = blockIdx.x * blockDim.x + threadIdx.x;
    if (e < N_EDGES) wn[e] = -dinv[src[e]] * dinv[dst[e]];
}

// ---------------- edge scatter (propagation) --------------------------------
// CH threads per edge, VEC floats per thread; DIN = CH*VEC.
template<int CH, int VEC>
__global__ void __launch_bounds__(256)
k_prop(const int* __restrict__ src, const int* __restrict__ dst,
       const float* __restrict__ wn, const float* __restrict__ t,
       float* __restrict__ out, float wscale) {
    long long idx = (long long)blockIdx.x * blockDim.x + threadIdx.x;
    int e = (int)(idx / CH);
    int c = (int)(idx - (long long)e * CH);
    if (e >= N_EDGES) return;
    int s = src[e], d = dst[e];
    float w = wn[e] * wscale;
    constexpr int DIN = CH * VEC;
    const float* tp = t + (size_t)s * DIN + c * VEC;
    float* op = out + (size_t)d * DIN + c * VEC;
    if constexpr (VEC == 4) {
        float4 v = *(const float4*)tp;
        asm volatile("red.global.add.v4.f32 [%0], {%1,%2,%3,%4};"
                     :: "l"(op), "f"(v.x * w), "f"(v.y * w), "f"(v.z * w), "f"(v.w * w)
                     : "memory");
    } else if constexpr (VEC == 2) {
        float2 v = *(const float2*)tp;
        asm volatile("red.global.add.v2.f32 [%0], {%1,%2};"
                     :: "l"(op), "f"(v.x * w), "f"(v.y * w)
                     : "memory");
    } else {
        atomicAdd(op, (*tp) * w);
    }
}

// ---------------- GEMM: acc(+)= T @ Wk --------------------------------------
// Tiled kernel for DIN=128, DOUT=64 (layer 1). 24 rows/block, 256 threads.
#define GN 24
__global__ void __launch_bounds__(256)
k_gemm_128_64(const float* __restrict__ T, const float* __restrict__ W,
              float* __restrict__ acc, int beta) {
    __shared__ __align__(16) float sT[GN][128];
    __shared__ __align__(16) float sWt[64][132];   // transposed W, padded
    int tx = threadIdx.x;             // 0..31
    int ty = threadIdx.y;             // 0..7
    int tid = ty * 32 + tx;
    int node0 = blockIdx.x * GN;

    for (int i = tid; i < 128 * 64; i += 256) {
        int r = i >> 6, c = i & 63;   // W[r][c]
        sWt[c][r] = W[i];
    }
    for (int i = tid; i < GN * 128; i += 256) {
        int r = i >> 7, c = i & 127;
        int n = node0 + r;
        sT[r][c] = (n < N_NODES) ? T[(size_t)n * 128 + c] : 0.f;
    }
    __syncthreads();

    float a[3][2] = {};
    #pragma unroll
    for (int i = 0; i < 128; i += 4) {
        float4 w0 = *(const float4*)&sWt[tx][i];
        float4 w1 = *(const float4*)&sWt[tx + 32][i];
        #pragma unroll
        for (int r = 0; r < 3; r++) {
            float4 tv = *(const float4*)&sT[ty + r * 8][i];
            a[r][0] += tv.x * w0.x + tv.y * w0.y + tv.z * w0.z + tv.w * w0.w;
            a[r][1] += tv.x * w1.x + tv.y * w1.y + tv.z * w1.z + tv.w * w1.w;
        }
    }
    #pragma unroll
    for (int r = 0; r < 3; r++) {
        int n = node0 + ty + r * 8;
        if (n < N_NODES) {
            size_t o = (size_t)n * 64 + tx;
            if (beta) { acc[o] += a[r][0]; acc[o + 32] += a[r][1]; }
            else      { acc[o]  = a[r][0]; acc[o + 32]  = a[r][1]; }
        }
    }
}

// Simple GEMM for small dims (W in smem, one thread per output element).
template<int DIN, int DOUT>
__global__ void __launch_bounds__(256)
k_gemm_simple(const float* __restrict__ T, const float* __restrict__ W,
              float* __restrict__ acc, int beta) {
    __shared__ float sW[DIN * DOUT];
    for (int i = threadIdx.x; i < DIN * DOUT; i += blockDim.x) sW[i] = W[i];
    __syncthreads();
    int idx = blockIdx.x * blockDim.x + threadIdx.x;
    int n = idx / DOUT, j = idx - n * DOUT;
    if (n >= N_NODES) return;
    const float* t = T + (size_t)n * DIN;
    float s = 0.f;
    #pragma unroll
    for (int i = 0; i < DIN; i++) s += __ldg(t + i) * sW[i * DOUT + j];
    size_t o = (size_t)n * DOUT + j;
    acc[o] = beta ? acc[o] + s : s;
}

// ---------------- bias + BN + ReLU epilogue ---------------------------------
template<int DOUT>
__global__ void __launch_bounds__(256)
k_post(const float* __restrict__ acc, const float* __restrict__ bias,
       const float* __restrict__ g, const float* __restrict__ b,
       const float* __restrict__ m, const float* __restrict__ v,
       float* __restrict__ out, int mode) {
    int idx = blockIdx.x * blockDim.x + threadIdx.x;
    if (idx >= N_NODES * DOUT) return;
    int j = idx % DOUT;
    float z = acc[idx] + bias[j];
    if (mode) {
        z = (z - m[j]) * (g[j] * rsqrtf(v[j] + 1e-5f)) + b[j];
        z = fmaxf(z, 0.f);
    }
    out[idx] = z;
}

// ---------------- host-side layer driver ------------------------------------
template<int DIN, int DOUT, int K, int CH, int VEC>
static void cheb_layer(const float* input, const float* W, const float* bias,
                       const float* bng, const float* bnb, const float* bnm, const float* bnv,
                       float* out, int mode,
                       const int* src, const int* dst, const float* wn,
                       float* bufA, float* bufB, float* bufC, float* acc) {
    static_assert(CH * VEC == DIN, "bad CH/VEC");
    const int NF = N_NODES * DIN;
    const int NF4 = NF / 4;

    auto gemm = [&](const float* T, int k, int beta) {
        const float* Wk = W + (size_t)k * DIN * DOUT;
        if constexpr (DIN == 128 && DOUT == 64) {
            dim3 blk(32, 8);
            k_gemm_128_64<<<(N_NODES + GN - 1) / GN, blk>>>(T, Wk, acc, beta);
        } else {
            int total = N_NODES * DOUT;
            k_gemm_simple<DIN, DOUT><<<(total + 255) / 256, 256>>>(T, Wk, acc, beta);
        }
    };

    long long ptot = (long long)N_EDGES * CH;
    int pgrid = (int)((ptot + 255) / 256);

    // k = 0
    gemm(input, 0, 0);
    // k = 1: Tx1 = L @ Tx0
    k_zero4<<<(NF4 + 255) / 256, 256>>>((float4*)bufA, NF4);
    k_prop<CH, VEC><<<pgrid, 256>>>(src, dst, wn, input, bufA, 1.f);
    gemm(bufA, 1, 1);

    // k >= 2: Tx2 = 2*L@Tx1 - Tx0 (init target to -Tx0, scatter with 2*w)
    const float* t0 = input;
    float* t1 = bufA;
    float* rot[3] = {bufA, bufB, bufC};
    int nx = 1;
    for (int k = 2; k < K; k++) {
        float* t2 = rot[nx];
        nx = (nx + 1) % 3;
        k_neg4<<<(NF4 + 255) / 256, 256>>>((const float4*)t0, (float4*)t2, NF4);
        k_prop<CH, VEC><<<pgrid, 256>>>(src, dst, wn, t1, t2, 2.f);
        gemm(t2, k, 1);
        t0 = t1;
        t1 = t2;
    }

    k_post<DOUT><<<(N_NODES * DOUT + 255) / 256, 256>>>(acc, bias, bng, bnb, bnm, bnv, out, mode);
}

extern "C" void kernel_launch(void* const* d_in, const int* in_sizes, int n_in,
                              void* d_out, int out_size) {
    const float* x   = (const float*)d_in[0];
    const int*   ei  = (const int*)d_in[1];
    const int*   src = ei;
    const int*   dst = ei + N_EDGES;
    const float* W1 = (const float*)d_in[2];  const float* b1 = (const float*)d_in[3];
    const float* W2 = (const float*)d_in[4];  const float* b2 = (const float*)d_in[5];
    const float* W3 = (const float*)d_in[6];  const float* b3 = (const float*)d_in[7];
    const float* W4 = (const float*)d_in[8];  const float* b4 = (const float*)d_in[9];
    const float* bn1g = (const float*)d_in[10]; const float* bn1b = (const float*)d_in[11];
    const float* bn1m = (const float*)d_in[12]; const float* bn1v = (const float*)d_in[13];
    const float* bn2g = (const float*)d_in[14]; const float* bn2b = (const float*)d_in[15];
    const float* bn2m = (const float*)d_in[16]; const float* bn2v = (const float*)d_in[17];
    const float* bn3g = (const float*)d_in[18]; const float* bn3b = (const float*)d_in[19];
    const float* bn3m = (const float*)d_in[20]; const float* bn3v = (const float*)d_in[21];

    float *deg, *dinv, *wn, *bufA, *bufB, *bufC, *acc, *h;
    cudaGetSymbolAddress((void**)&deg,  g_deg);
    cudaGetSymbolAddress((void**)&dinv, g_dinv);
    cudaGetSymbolAddress((void**)&wn,   g_wn);
    cudaGetSymbolAddress((void**)&bufA, g_bufA);
    cudaGetSymbolAddress((void**)&bufB, g_bufB);
    cudaGetSymbolAddress((void**)&bufC, g_bufC);
    cudaGetSymbolAddress((void**)&acc,  g_acc);
    cudaGetSymbolAddress((void**)&h,    g_h);

    // graph normalization
    k_zero4<<<(N_NODES / 4 + 255) / 256, 256>>>((float4*)deg, N_NODES / 4);
    k_deg  <<<(N_EDGES + 255) / 256, 256>>>(dst, deg);
    k_dinv <<<(N_NODES + 255) / 256, 256>>>(deg, dinv);
    k_wnorm<<<(N_EDGES + 255) / 256, 256>>>(src, dst, dinv, wn);

    // layer 1: 128 -> 64, K=8, BN+ReLU
    cheb_layer<128, 64, 8, 32, 4>(x, W1, b1, bn1g, bn1b, bn1m, bn1v, h, 1,
                                  src, dst, wn, bufA, bufB, bufC, acc);
    // layer 2: 64 -> 18, K=6, BN+ReLU
    cheb_layer<64, 18, 6, 16, 4>(h, W2, b2, bn2g, bn2b, bn2m, bn2v, h, 1,
                                 src, dst, wn, bufA, bufB, bufC, acc);
    // layer 3: 18 -> 9, K=4, BN+ReLU
    cheb_layer<18, 9, 4, 9, 2>(h, W3, b3, bn3g, bn3b, bn3m, bn3v, h, 1,
                               src, dst, wn, bufA, bufB, bufC, acc);
    // layer 4: 9 -> 10, K=4, bias only, write d_out
    cheb_layer<9, 10, 4, 9, 1>(h, W4, b4, nullptr, nullptr, nullptr, nullptr,
                               (float*)d_out, 0,
                               src, dst, wn, bufA, bufB, bufC, acc);
}

// round 2
// speedup vs baseline: 1.0421x; 1.0421x over previous
#include <cuda_runtime.h>

#define N_NODES 100000
#define N_EDGES 1600000

// ---------------- scratch (device globals; no runtime allocation) ----------
__device__ float g_deg [N_NODES];
__device__ float g_dinv[N_NODES];
__device__ float g_wn  [N_EDGES];
__device__ float g_bufA[(size_t)N_NODES * 64];
__device__ float g_bufB[(size_t)N_NODES * 64];
__device__ float g_bufC[(size_t)N_NODES * 64];
__device__ float g_acc [(size_t)N_NODES * 64];
__device__ float g_h   [(size_t)N_NODES * 64];

// ---------------- elementwise helpers --------------------------------------
__global__ void k_zero4(float4* __restrict__ p, int n4) {
    int i = blockIdx.x * blockDim.x + threadIdx.x;
    if (i < n4) p[i] = make_float4(0.f, 0.f, 0.f, 0.f);
}

// ---------------- graph normalization ---------------------------------------
__global__ void k_deg(const int* __restrict__ dst, float* __restrict__ deg) {
    int e = blockIdx.x * blockDim.x + threadIdx.x;
    if (e < N_EDGES) atomicAdd(&deg[dst[e]], 1.0f);
}

__global__ void k_dinv(const float* __restrict__ deg, float* __restrict__ dinv) {
    int i = blockIdx.x * blockDim.x + threadIdx.x;
    if (i < N_NODES) {
        float d = deg[i];
        dinv[i] = (d > 0.f) ? rsqrtf(fmaxf(d, 1.f)) : 0.f;
    }
}

__global__ void k_wnorm(const int* __restrict__ src, const int* __restrict__ dst,
                        const float* __restrict__ dinv, float* __restrict__ wn) {
    int e = blockIdx.x * blockDim.x + threadIdx.x;
    if (e < N_EDGES) wn[e] = -dinv[src[e]] * dinv[dst[e]];
}

// ---------------- edge scatter (propagation) --------------------------------
// CH threads per edge, VEC floats per thread; DIM = CH*VEC.
template<int CH, int VEC>
__global__ void __launch_bounds__(256)
k_prop(const int* __restrict__ src, const int* __restrict__ dst,
       const float* __restrict__ wn, const float* __restrict__ t,
       float* __restrict__ out, float wscale) {
    long long idx = (long long)blockIdx.x * blockDim.x + threadIdx.x;
    int e = (int)(idx / CH);
    int c = (int)(idx - (long long)e * CH);
    if (e >= N_EDGES) return;
    int s = src[e], d = dst[e];
    float w = wn[e] * wscale;
    constexpr int DIM = CH * VEC;
    const float* tp = t + (size_t)s * DIM + c * VEC;
    float* op = out + (size_t)d * DIM + c * VEC;
    if constexpr (VEC == 4) {
        float4 v = *(const float4*)tp;
        asm volatile("red.global.add.v4.f32 [%0], {%1,%2,%3,%4};"
                     :: "l"(op), "f"(v.x * w), "f"(v.y * w), "f"(v.z * w), "f"(v.w * w)
                     : "memory");
    } else if constexpr (VEC == 2) {
        float2 v = *(const float2*)tp;
        asm volatile("red.global.add.v2.f32 [%0], {%1,%2};"
                     :: "l"(op), "f"(v.x * w), "f"(v.y * w)
                     : "memory");
    } else {
        atomicAdd(op, (*tp) * w);
    }
}

// ---------------- GEMM: out = T @ Wk - sub ----------------------------------
// Tiled kernel for DIN=128, DOUT=64 (layer 1). 24 rows/block, 256 threads.
#define GN 24
__global__ void __launch_bounds__(256)
k_gemm_128_64(const float* __restrict__ T, const float* __restrict__ W,
              float* __restrict__ out, const float* __restrict__ sub) {
    __shared__ __align__(16) float sT[GN][128];
    __shared__ __align__(16) float sWt[64][132];   // transposed W, padded
    int tx = threadIdx.x;             // 0..31
    int ty = threadIdx.y;             // 0..7
    int tid = ty * 32 + tx;
    int node0 = blockIdx.x * GN;

    for (int i = tid; i < 128 * 64; i += 256) {
        int r = i >> 6, c = i & 63;   // W[r][c]
        sWt[c][r] = W[i];
    }
    for (int i = tid; i < GN * 128; i += 256) {
        int r = i >> 7, c = i & 127;
        int n = node0 + r;
        sT[r][c] = (n < N_NODES) ? T[(size_t)n * 128 + c] : 0.f;
    }
    __syncthreads();

    float a[3][2] = {};
    #pragma unroll
    for (int i = 0; i < 128; i += 4) {
        float4 w0 = *(const float4*)&sWt[tx][i];
        float4 w1 = *(const float4*)&sWt[tx + 32][i];
        #pragma unroll
        for (int r = 0; r < 3; r++) {
            float4 tv = *(const float4*)&sT[ty + r * 8][i];
            a[r][0] += tv.x * w0.x + tv.y * w0.y + tv.z * w0.z + tv.w * w0.w;
            a[r][1] += tv.x * w1.x + tv.y * w1.y + tv.z * w1.z + tv.w * w1.w;
        }
    }
    #pragma unroll
    for (int r = 0; r < 3; r++) {
        int n = node0 + ty + r * 8;
        if (n < N_NODES) {
            size_t o = (size_t)n * 64 + tx;
            if (sub) { out[o] = a[r][0] - sub[o]; out[o + 32] = a[r][1] - sub[o + 32]; }
            else     { out[o] = a[r][0];          out[o + 32] = a[r][1]; }
        }
    }
}

// Simple GEMM for small dims (W in smem, one thread per output element).
template<int DIN, int DOUT>
__global__ void __launch_bounds__(256)
k_gemm_simple(const float* __restrict__ T, const float* __restrict__ W,
              float* __restrict__ out, const float* __restrict__ sub) {
    __shared__ float sW[DIN * DOUT];
    for (int i = threadIdx.x; i < DIN * DOUT; i += blockDim.x) sW[i] = W[i];
    __syncthreads();
    int idx = blockIdx.x * blockDim.x + threadIdx.x;
    int n = idx / DOUT, j = idx - n * DOUT;
    if (n >= N_NODES) return;
    const float* t = T + (size_t)n * DIN;
    float s = 0.f;
    #pragma unroll
    for (int i = 0; i < DIN; i++) s += __ldg(t + i) * sW[i * DOUT + j];
    size_t o = (size_t)n * DOUT + j;
    out[o] = sub ? (s - sub[o]) : s;
}

// ---------------- bias + BN + ReLU epilogue ---------------------------------
template<int DOUT>
__global__ void __launch_bounds__(256)
k_post(const float* __restrict__ acc, const float* __restrict__ bias,
       const float* __restrict__ g, const float* __restrict__ b,
       const float* __restrict__ m, const float* __restrict__ v,
       float* __restrict__ out, int mode) {
    int idx = blockIdx.x * blockDim.x + threadIdx.x;
    if (idx >= N_NODES * DOUT) return;
    int j = idx % DOUT;
    float z = acc[idx] + bias[j];
    if (mode) {
        z = (z - m[j]) * (g[j] * rsqrtf(v[j] + 1e-5f)) + b[j];
        z = fmaxf(z, 0.f);
    }
    out[idx] = z;
}

// ---------------- host-side layer driver (Clenshaw) -------------------------
// out = sum_k T_k(L) X W_k computed as:
//   b_k = X@W_k - b_{k+2} + 2 L b_{k+1}   (k = K-1 .. 1)
//   acc = X@W_0 - b_2 + L b_1
// Props run at DOUT width (CH*VEC == DOUT).
template<int DIN, int DOUT, int K, int CH, int VEC>
static void cheb_layer(const float* input, const float* W, const float* bias,
                       const float* bng, const float* bnb, const float* bnm, const float* bnv,
                       float* out, int mode,
                       const int* src, const int* dst, const float* wn,
                       float* r0, float* r1, float* r2, float* acc) {
    static_assert(CH * VEC == DOUT, "bad CH/VEC");

    auto gemm = [&](int k, float* o, const float* sub) {
        const float* Wk = W + (size_t)k * DIN * DOUT;
        if constexpr (DIN == 128 && DOUT == 64) {
            dim3 blk(32, 8);
            k_gemm_128_64<<<(N_NODES + GN - 1) / GN, blk>>>(input, Wk, o, sub);
        } else {
            int total = N_NODES * DOUT;
            k_gemm_simple<DIN, DOUT><<<(total + 255) / 256, 256>>>(input, Wk, o, sub);
        }
    };

    long long ptot = (long long)N_EDGES * CH;
    int pgrid = (int)((ptot + 255) / 256);
    auto prop = [&](const float* tin, float* tout, float wscale) {
        k_prop<CH, VEC><<<pgrid, 256>>>(src, dst, wn, tin, tout, wscale);
    };

    float* rot[3] = {r0, r1, r2};
    int nx = 0;
    float* b_kp1 = nullptr;   // b_{k+1}
    float* b_kp2 = nullptr;   // b_{k+2}
    for (int k = K - 1; k >= 1; k--) {
        float* t = rot[nx];
        nx = (nx + 1) % 3;
        gemm(k, t, b_kp2);                    // t = X@W_k - b_{k+2}
        if (b_kp1) prop(b_kp1, t, 2.f);       // t += 2 L b_{k+1}
        b_kp2 = b_kp1;
        b_kp1 = t;
    }
    gemm(0, acc, b_kp2);                      // acc = X@W_0 - b_2
    prop(b_kp1, acc, 1.f);                    // acc += L b_1

    k_post<DOUT><<<(N_NODES * DOUT + 255) / 256, 256>>>(acc, bias, bng, bnb, bnm, bnv, out, mode);
}

extern "C" void kernel_launch(void* const* d_in, const int* in_sizes, int n_in,
                              void* d_out, int out_size) {
    const float* x   = (const float*)d_in[0];
    const int*   ei  = (const int*)d_in[1];
    const int*   src = ei;
    const int*   dst = ei + N_EDGES;
    const float* W1 = (const float*)d_in[2];  const float* b1 = (const float*)d_in[3];
    const float* W2 = (const float*)d_in[4];  const float* b2 = (const float*)d_in[5];
    const float* W3 = (const float*)d_in[6];  const float* b3 = (const float*)d_in[7];
    const float* W4 = (const float*)d_in[8];  const float* b4 = (const float*)d_in[9];
    const float* bn1g = (const float*)d_in[10]; const float* bn1b = (const float*)d_in[11];
    const float* bn1m = (const float*)d_in[12]; const float* bn1v = (const float*)d_in[13];
    const float* bn2g = (const float*)d_in[14]; const float* bn2b = (const float*)d_in[15];
    const float* bn2m = (const float*)d_in[16]; const float* bn2v = (const float*)d_in[17];
    const float* bn3g = (const float*)d_in[18]; const float* bn3b = (const float*)d_in[19];
    const float* bn3m = (const float*)d_in[20]; const float* bn3v = (const float*)d_in[21];

    float *deg, *dinv, *wn, *bufA, *bufB, *bufC, *acc, *h;
    cudaGetSymbolAddress((void**)&deg,  g_deg);
    cudaGetSymbolAddress((void**)&dinv, g_dinv);
    cudaGetSymbolAddress((void**)&wn,   g_wn);
    cudaGetSymbolAddress((void**)&bufA, g_bufA);
    cudaGetSymbolAddress((void**)&bufB, g_bufB);
    cudaGetSymbolAddress((void**)&bufC, g_bufC);
    cudaGetSymbolAddress((void**)&acc,  g_acc);
    cudaGetSymbolAddress((void**)&h,    g_h);

    // graph normalization
    k_zero4<<<(N_NODES / 4 + 255) / 256, 256>>>((float4*)deg, N_NODES / 4);
    k_deg  <<<(N_EDGES + 255) / 256, 256>>>(dst, deg);
    k_dinv <<<(N_NODES + 255) / 256, 256>>>(deg, dinv);
    k_wnorm<<<(N_EDGES + 255) / 256, 256>>>(src, dst, dinv, wn);

    // layer 1: 128 -> 64, K=8, BN+ReLU (props at width 64)
    cheb_layer<128, 64, 8, 16, 4>(x, W1, b1, bn1g, bn1b, bn1m, bn1v, h, 1,
                                  src, dst, wn, bufA, bufB, bufC, acc);
    // layer 2: 64 -> 18, K=6, BN+ReLU (props at width 18)
    cheb_layer<64, 18, 6, 9, 2>(h, W2, b2, bn2g, bn2b, bn2m, bn2v, h, 1,
                                src, dst, wn, bufA, bufB, bufC, acc);
    // layer 3: 18 -> 9, K=4, BN+ReLU (props at width 9)
    cheb_layer<18, 9, 4, 9, 1>(h, W3, b3, bn3g, bn3b, bn3m, bn3v, h, 1,
                               src, dst, wn, bufA, bufB, bufC, acc);
    // layer 4: 9 -> 10, K=4, bias only, write d_out (props at width 10)
    cheb_layer<9, 10, 4, 5, 2>(h, W4, b4, nullptr, nullptr, nullptr, nullptr,
                               (float*)d_out, 0,
                               src, dst, wn, bufA, bufB, bufC, acc);
}

// round 3
// speedup vs baseline: 2.5848x; 2.4804x over previous
#include <cuda_runtime.h>

#define N_NODES 100000
#define N_EDGES 1600000
#define SCAN_B  1024
#define NBLK    ((N_NODES + SCAN_B - 1) / SCAN_B)   // 98

// ---------------- scratch (device globals; no runtime allocation) ----------
__device__ int   g_degi  [N_NODES];
__device__ float g_dinv  [N_NODES];
__device__ int   g_rowptr[N_NODES + 1];
__device__ int   g_cursor[N_NODES];
__device__ int   g_partial[128];
__device__ int   g_csrc[N_EDGES];
__device__ float g_cw  [N_EDGES];
__device__ float g_bufA[(size_t)N_NODES * 64];
__device__ float g_bufB[(size_t)N_NODES * 64];
__device__ float g_bufC[(size_t)N_NODES * 64];
__device__ float g_acc [(size_t)N_NODES * 64];
__device__ float g_h   [(size_t)N_NODES * 64];

// ---------------- small helpers ---------------------------------------------
__global__ void k_zeroi(int* __restrict__ p, int n) {
    int i = blockIdx.x * blockDim.x + threadIdx.x;
    if (i < n) p[i] = 0;
}

// ---------------- CSR build --------------------------------------------------
__global__ void k_hist(const int* __restrict__ dst, int* __restrict__ degi) {
    int e = blockIdx.x * blockDim.x + threadIdx.x;
    if (e < N_EDGES) atomicAdd(&degi[dst[e]], 1);
}

__global__ void k_dinv_k(const int* __restrict__ degi, float* __restrict__ dinv) {
    int i = blockIdx.x * blockDim.x + threadIdx.x;
    if (i < N_NODES) {
        int d = degi[i];
        dinv[i] = (d > 0) ? rsqrtf((float)d) : 0.f;
    }
}

__global__ void k_scan1(const int* __restrict__ degi, int* __restrict__ rowptr,
                        int* __restrict__ partial) {
    __shared__ int s[SCAN_B];
    int t = threadIdx.x;
    int i = blockIdx.x * SCAN_B + t;
    int v = (i < N_NODES) ? degi[i] : 0;
    s[t] = v;
    __syncthreads();
    for (int off = 1; off < SCAN_B; off <<= 1) {
        int x = (t >= off) ? s[t - off] : 0;
        __syncthreads();
        s[t] += x;
        __syncthreads();
    }
    if (i < N_NODES) rowptr[i + 1] = s[t];
    if (t == SCAN_B - 1) partial[blockIdx.x] = s[t];
}

__global__ void k_scan2(int* __restrict__ partial) {
    __shared__ int s[128];
    int t = threadIdx.x;
    int v = (t < NBLK) ? partial[t] : 0;
    s[t] = v;
    __syncthreads();
    for (int off = 1; off < 128; off <<= 1) {
        int x = (t >= off) ? s[t - off] : 0;
        __syncthreads();
        s[t] += x;
        __syncthreads();
    }
    if (t < NBLK) partial[t] = s[t] - v;   // exclusive
}

__global__ void k_scan3(int* __restrict__ rowptr, const int* __restrict__ partial) {
    int i = blockIdx.x * blockDim.x + threadIdx.x;
    if (i < N_NODES) rowptr[i + 1] += partial[i / SCAN_B];
    if (i == 0) rowptr[0] = 0;
}

__global__ void k_fill(const int* __restrict__ src, const int* __restrict__ dst,
                       const float* __restrict__ dinv, const int* __restrict__ rowptr,
                       int* __restrict__ cursor, int* __restrict__ csrc,
                       float* __restrict__ cw) {
    int e = blockIdx.x * blockDim.x + threadIdx.x;
    if (e >= N_EDGES) return;
    int s = src[e], d = dst[e];
    int pos = atomicAdd(&cursor[d], 1);
    int idx = rowptr[d] + pos;
    csrc[idx] = s;
    cw[idx]   = -dinv[s] * dinv[d];
}

// ---------------- CSR gather propagation ------------------------------------
// LANES threads per node, VEC floats per thread; DIM = LANES*VEC.
// out[n] += wscale * sum_j w_j * tin[src_j]   (in-place accumulate, no atomics)
template<int LANES, int VEC>
__global__ void __launch_bounds__(256)
k_prop_csr(const int* __restrict__ rowptr, const int* __restrict__ csrc,
           const float* __restrict__ cw, const float* __restrict__ tin,
           float* __restrict__ out, float wscale) {
    long long idx = (long long)blockIdx.x * blockDim.x + threadIdx.x;
    int n = (int)(idx / LANES);
    int l = (int)(idx - (long long)n * LANES);
    if (n >= N_NODES) return;
    int j0 = rowptr[n], j1 = rowptr[n + 1];
    constexpr int DIM = LANES * VEC;
    float acc[VEC];
    #pragma unroll
    for (int v = 0; v < VEC; v++) acc[v] = 0.f;
    for (int j = j0; j < j1; j++) {
        int s  = __ldg(&csrc[j]);
        float w = __ldg(&cw[j]);
        const float* tp = tin + (size_t)s * DIM + l * VEC;
        if constexpr (VEC == 4) {
            float4 t4 = *(const float4*)tp;
            acc[0] += w * t4.x; acc[1] += w * t4.y;
            acc[2] += w * t4.z; acc[3] += w * t4.w;
        } else if constexpr (VEC == 2) {
            float2 t2 = *(const float2*)tp;
            acc[0] += w * t2.x; acc[1] += w * t2.y;
        } else {
            acc[0] += w * (*tp);
        }
    }
    float* op = out + (size_t)n * DIM + l * VEC;
    #pragma unroll
    for (int v = 0; v < VEC; v++) op[v] += wscale * acc[v];
}

// ---------------- layer-1 GEMM: out = T(128) @ W(128x64) - sub --------------
// block (16,16); 48 rows x 64 cols per block; K split into 2 chunks of 64.
#define L1_RB 48
__global__ void __launch_bounds__(256)
k_gemm_l1(const float* __restrict__ T, const float* __restrict__ W,
          float* __restrict__ out, const float* __restrict__ sub) {
    __shared__ __align__(16) float sT[L1_RB][68];   // pad: stride 68 (bank-shift 4)
    __shared__ __align__(16) float sW[64][64];
    int tx = threadIdx.x;   // 0..15 -> 4 cols each
    int ty = threadIdx.y;   // 0..15 -> 3 rows each (stride 16)
    int tid = ty * 16 + tx;
    int node0 = blockIdx.x * L1_RB;

    float acc[3][4] = {};

    #pragma unroll
    for (int kk = 0; kk < 2; kk++) {
        // stage W chunk [64 k][64 c]
        for (int i = tid; i < 64 * 16; i += 256) {
            int r = i >> 4, c4 = (i & 15) * 4;
            *(float4*)&sW[r][c4] = *(const float4*)&W[(kk * 64 + r) * 64 + c4];
        }
        // stage T chunk [48 rows][64 k]
        for (int i = tid; i < L1_RB * 16; i += 256) {
            int r = i >> 4, c4 = (i & 15) * 4;
            int n = node0 + r;
            float4 v = make_float4(0.f, 0.f, 0.f, 0.f);
            if (n < N_NODES) v = *(const float4*)&T[(size_t)n * 128 + kk * 64 + c4];
            *(float4*)&sT[r][c4] = v;
        }
        __syncthreads();

        #pragma unroll
        for (int k = 0; k < 64; k += 4) {
            float4 w0 = *(const float4*)&sW[k + 0][tx * 4];
            float4 w1 = *(const float4*)&sW[k + 1][tx * 4];
            float4 w2 = *(const float4*)&sW[k + 2][tx * 4];
            float4 w3 = *(const float4*)&sW[k + 3][tx * 4];
            #pragma unroll
            for (int r = 0; r < 3; r++) {
                float4 t4 = *(const float4*)&sT[ty + r * 16][k];
                acc[r][0] += t4.x * w0.x + t4.y * w1.x + t4.z * w2.x + t4.w * w3.x;
                acc[r][1] += t4.x * w0.y + t4.y * w1.y + t4.z * w2.y + t4.w * w3.y;
                acc[r][2] += t4.x * w0.z + t4.y * w1.z + t4.z * w2.z + t4.w * w3.z;
                acc[r][3] += t4.x * w0.w + t4.y * w1.w + t4.z * w2.w + t4.w * w3.w;
            }
        }
        __syncthreads();
    }

    #pragma unroll
    for (int r = 0; r < 3; r++) {
        int n = node0 + ty + r * 16;
        if (n < N_NODES) {
            size_t o = (size_t)n * 64 + tx * 4;
            float4 res = make_float4(acc[r][0], acc[r][1], acc[r][2], acc[r][3]);
            if (sub) {
                float4 sv = *(const float4*)&sub[o];
                res.x -= sv.x; res.y -= sv.y; res.z -= sv.z; res.w -= sv.w;
            }
            *(float4*)&out[o] = res;
        }
    }
}

// ---------------- simple GEMM for small dims --------------------------------
template<int DIN, int DOUT>
__global__ void __launch_bounds__(256)
k_gemm_simple(const float* __restrict__ T, const float* __restrict__ W,
              float* __restrict__ out, const float* __restrict__ sub) {
    __shared__ float sW[DIN * DOUT];
    for (int i = threadIdx.x; i < DIN * DOUT; i += blockDim.x) sW[i] = W[i];
    __syncthreads();
    int idx = blockIdx.x * blockDim.x + threadIdx.x;
    int n = idx / DOUT, j = idx - n * DOUT;
    if (n >= N_NODES) return;
    const float* t = T + (size_t)n * DIN;
    float s = 0.f;
    #pragma unroll
    for (int i = 0; i < DIN; i++) s += __ldg(t + i) * sW[i * DOUT + j];
    size_t o = (size_t)n * DOUT + j;
    out[o] = sub ? (s - sub[o]) : s;
}

// ---------------- bias + BN + ReLU epilogue ---------------------------------
template<int DOUT>
__global__ void __launch_bounds__(256)
k_post(const float* __restrict__ acc, const float* __restrict__ bias,
       const float* __restrict__ g, const float* __restrict__ b,
       const float* __restrict__ m, const float* __restrict__ v,
       float* __restrict__ out, int mode) {
    int idx = blockIdx.x * blockDim.x + threadIdx.x;
    if (idx >= N_NODES * DOUT) return;
    int j = idx % DOUT;
    float z = acc[idx] + bias[j];
    if (mode) {
        z = (z - m[j]) * (g[j] * rsqrtf(v[j] + 1e-5f)) + b[j];
        z = fmaxf(z, 0.f);
    }
    out[idx] = z;
}

// ---------------- host-side layer driver (Clenshaw + CSR) -------------------
template<int DIN, int DOUT, int K, int LANES, int VEC>
static void cheb_layer(const float* input, const float* W, const float* bias,
                       const float* bng, const float* bnb, const float* bnm, const float* bnv,
                       float* out, int mode,
                       const int* rowptr, const int* csrc, const float* cw,
                       float* r0, float* r1, float* r2, float* acc) {
    static_assert(LANES * VEC == DOUT, "bad LANES/VEC");

    auto gemm = [&](int k, float* o, const float* sub) {
        const float* Wk = W + (size_t)k * DIN * DOUT;
        if constexpr (DIN == 128 && DOUT == 64) {
            dim3 blk(16, 16);
            k_gemm_l1<<<(N_NODES + L1_RB - 1) / L1_RB, blk>>>(input, Wk, o, sub);
        } else {
            int total = N_NODES * DOUT;
            k_gemm_simple<DIN, DOUT><<<(total + 255) / 256, 256>>>(input, Wk, o, sub);
        }
    };

    long long ptot = (long long)N_NODES * LANES;
    int pgrid = (int)((ptot + 255) / 256);
    auto prop = [&](const float* tin, float* tout, float wscale) {
        k_prop_csr<LANES, VEC><<<pgrid, 256>>>(rowptr, csrc, cw, tin, tout, wscale);
    };

    float* rot[3] = {r0, r1, r2};
    int nx = 0;
    float* b_kp1 = nullptr;
    float* b_kp2 = nullptr;
    for (int k = K - 1; k >= 1; k--) {
        float* t = rot[nx];
        nx = (nx + 1) % 3;
        gemm(k, t, b_kp2);                 // t = X@W_k - b_{k+2}
        if (b_kp1) prop(b_kp1, t, 2.f);    // t += 2 L b_{k+1}
        b_kp2 = b_kp1;
        b_kp1 = t;
    }
    gemm(0, acc, b_kp2);                   // acc = X@W_0 - b_2
    prop(b_kp1, acc, 1.f);                 // acc += L b_1

    k_post<DOUT><<<(N_NODES * DOUT + 255) / 256, 256>>>(acc, bias, bng, bnb, bnm, bnv, out, mode);
}

extern "C" void kernel_launch(void* const* d_in, const int* in_sizes, int n_in,
                              void* d_out, int out_size) {
    const float* x   = (const float*)d_in[0];
    const int*   ei  = (const int*)d_in[1];
    const int*   src = ei;
    const int*   dst = ei + N_EDGES;
    const float* W1 = (const float*)d_in[2];  const float* b1 = (const float*)d_in[3];
    const float* W2 = (const float*)d_in[4];  const float* b2 = (const float*)d_in[5];
    const float* W3 = (const float*)d_in[6];  const float* b3 = (const float*)d_in[7];
    const float* W4 = (const float*)d_in[8];  const float* b4 = (const float*)d_in[9];
    const float* bn1g = (const float*)d_in[10]; const float* bn1b = (const float*)d_in[11];
    const float* bn1m = (const float*)d_in[12]; const float* bn1v = (const float*)d_in[13];
    const float* bn2g = (const float*)d_in[14]; const float* bn2b = (const float*)d_in[15];
    const float* bn2m = (const float*)d_in[16]; const float* bn2v = (const float*)d_in[17];
    const float* bn3g = (const float*)d_in[18]; const float* bn3b = (const float*)d_in[19];
    const float* bn3m = (const float*)d_in[20]; const float* bn3v = (const float*)d_in[21];

    int *degi, *rowptr, *cursor, *partial, *csrc;
    float *dinv, *cw, *bufA, *bufB, *bufC, *acc, *h;
    cudaGetSymbolAddress((void**)&degi,   g_degi);
    cudaGetSymbolAddress((void**)&dinv,   g_dinv);
    cudaGetSymbolAddress((void**)&rowptr, g_rowptr);
    cudaGetSymbolAddress((void**)&cursor, g_cursor);
    cudaGetSymbolAddress((void**)&partial,g_partial);
    cudaGetSymbolAddress((void**)&csrc,   g_csrc);
    cudaGetSymbolAddress((void**)&cw,     g_cw);
    cudaGetSymbolAddress((void**)&bufA,   g_bufA);
    cudaGetSymbolAddress((void**)&bufB,   g_bufB);
    cudaGetSymbolAddress((void**)&bufC,   g_bufC);
    cudaGetSymbolAddress((void**)&acc,    g_acc);
    cudaGetSymbolAddress((void**)&h,      g_h);

    // ---- CSR build ----
    k_zeroi<<<(N_NODES + 255) / 256, 256>>>(degi, N_NODES);
    k_zeroi<<<(N_NODES + 255) / 256, 256>>>(cursor, N_NODES);
    k_hist  <<<(N_EDGES + 255) / 256, 256>>>(dst, degi);
    k_dinv_k<<<(N_NODES + 255) / 256, 256>>>(degi, dinv);
    k_scan1 <<<NBLK, SCAN_B>>>(degi, rowptr, partial);
    k_scan2 <<<1, 128>>>(partial);
    k_scan3 <<<(N_NODES + 255) / 256, 256>>>(rowptr, partial);
    k_fill  <<<(N_EDGES + 255) / 256, 256>>>(src, dst, dinv, rowptr, cursor, csrc, cw);

    // layer 1: 128 -> 64, K=8, BN+ReLU (props at width 64)
    cheb_layer<128, 64, 8, 16, 4>(x, W1, b1, bn1g, bn1b, bn1m, bn1v, h, 1,
                                  rowptr, csrc, cw, bufA, bufB, bufC, acc);
    // layer 2: 64 -> 18, K=6, BN+ReLU (props at width 18)
    cheb_layer<64, 18, 6, 9, 2>(h, W2, b2, bn2g, bn2b, bn2m, bn2v, h, 1,
                                rowptr, csrc, cw, bufA, bufB, bufC, acc);
    // layer 3: 18 -> 9, K=4, BN+ReLU (props at width 9)
    cheb_layer<18, 9, 4, 9, 1>(h, W3, b3, bn3g, bn3b, bn3m, bn3v, h, 1,
                               rowptr, csrc, cw, bufA, bufB, bufC, acc);
    // layer 4: 9 -> 10, K=4, bias only, write d_out (props at width 10)
    cheb_layer<9, 10, 4, 5, 2>(h, W4, b4, nullptr, nullptr, nullptr, nullptr,
                               (float*)d_out, 0,
                               rowptr, csrc, cw, bufA, bufB, bufC, acc);
}

// round 5
// speedup vs baseline: 2.7010x; 1.0450x over previous
#include <cuda_runtime.h>

#define N_NODES 100000
#define N_EDGES 1600000
#define SCAN_B  1024
#define NBLK    ((N_NODES + SCAN_B - 1) / SCAN_B)   // 98

// ---------------- scratch (device globals; no runtime allocation) ----------
__device__ int   g_degi  [N_NODES];
__device__ float g_dinv  [N_NODES];
__device__ int   g_rowptr[N_NODES + 1];
__device__ int   g_cursor[N_NODES];
__device__ int   g_partial[128];
__device__ int   g_csrc[N_EDGES];
__device__ float g_cw  [N_EDGES];
__device__ float g_xw  [(size_t)N_NODES * 512];   // concat GEMM output (max 8*64)
__device__ float g_bufA[(size_t)N_NODES * 64];
__device__ float g_bufB[(size_t)N_NODES * 64];
__device__ float g_bufC[(size_t)N_NODES * 64];
__device__ float g_h   [(size_t)N_NODES * 64];

// ---------------- small helpers ---------------------------------------------
__global__ void k_zeroi(int* __restrict__ p, int n) {
    int i = blockIdx.x * blockDim.x + threadIdx.x;
    if (i < n) p[i] = 0;
}

// ---------------- CSR build --------------------------------------------------
__global__ void k_hist(const int* __restrict__ dst, int* __restrict__ degi) {
    int e = blockIdx.x * blockDim.x + threadIdx.x;
    if (e < N_EDGES) atomicAdd(&degi[dst[e]], 1);
}

__global__ void k_dinv_k(const int* __restrict__ degi, float* __restrict__ dinv) {
    int i = blockIdx.x * blockDim.x + threadIdx.x;
    if (i < N_NODES) {
        int d = degi[i];
        dinv[i] = (d > 0) ? rsqrtf((float)d) : 0.f;
    }
}

__global__ void k_scan1(const int* __restrict__ degi, int* __restrict__ rowptr,
                        int* __restrict__ partial) {
    __shared__ int s[SCAN_B];
    int t = threadIdx.x;
    int i = blockIdx.x * SCAN_B + t;
    int v = (i < N_NODES) ? degi[i] : 0;
    s[t] = v;
    __syncthreads();
    for (int off = 1; off < SCAN_B; off <<= 1) {
        int x = (t >= off) ? s[t - off] : 0;
        __syncthreads();
        s[t] += x;
        __syncthreads();
    }
    if (i < N_NODES) rowptr[i + 1] = s[t];
    if (t == SCAN_B - 1) partial[blockIdx.x] = s[t];
}

__global__ void k_scan2(int* __restrict__ partial) {
    __shared__ int s[128];
    int t = threadIdx.x;
    int v = (t < NBLK) ? partial[t] : 0;
    s[t] = v;
    __syncthreads();
    for (int off = 1; off < 128; off <<= 1) {
        int x = (t >= off) ? s[t - off] : 0;
        __syncthreads();
        s[t] += x;
        __syncthreads();
    }
    if (t < NBLK) partial[t] = s[t] - v;   // exclusive
}

__global__ void k_scan3(int* __restrict__ rowptr, const int* __restrict__ partial) {
    int i = blockIdx.x * blockDim.x + threadIdx.x;
    if (i < N_NODES) rowptr[i + 1] += partial[i / SCAN_B];
    if (i == 0) rowptr[0] = 0;
}

__global__ void k_fill(const int* __restrict__ src, const int* __restrict__ dst,
                       const float* __restrict__ dinv, const int* __restrict__ rowptr,
                       int* __restrict__ cursor, int* __restrict__ csrc,
                       float* __restrict__ cw) {
    int e = blockIdx.x * blockDim.x + threadIdx.x;
    if (e >= N_EDGES) return;
    int s = src[e], d = dst[e];
    int pos = atomicAdd(&cursor[d], 1);
    int idx = rowptr[d] + pos;
    csrc[idx] = s;
    cw[idx]   = -dinv[s] * dinv[d];
}

// ---------------- big concat GEMM: xw[n][c] = sum_i T[n][i]*W[c/DOUT][i][c%DOUT]
// 64x64 tile, 256 threads, 4x4 register blocking, K chunked by 64.
template<int DIN, int NT, int DOUT>
__global__ void __launch_bounds__(256)
k_gemm_big(const float* __restrict__ T, const float* __restrict__ Wb,
           float* __restrict__ out) {
    constexpr int KC = 64;
    constexpr int NKC = DIN / KC ? DIN / KC : 1;
    constexpr int KCC = (DIN < KC) ? DIN : KC;
    __shared__ __align__(16) float sX[KCC][64 + 4];   // transposed [k][row]
    __shared__ __align__(16) float sW[KCC][64];
    int tid = threadIdx.x;
    int tx = tid & 15, ty = tid >> 4;
    int row0 = blockIdx.x * 64;
    int col0 = blockIdx.y * 64;

    float acc[4][4] = {};

    for (int kc = 0; kc < NKC; kc++) {
        // stage X tile transposed
        for (int i = tid; i < 64 * (KCC / 4); i += 256) {
            int r  = i / (KCC / 4);
            int k4 = (i % (KCC / 4)) * 4;
            int n = row0 + r;
            float4 v = make_float4(0.f, 0.f, 0.f, 0.f);
            if (n < N_NODES) v = *(const float4*)&T[(size_t)n * DIN + kc * KC + k4];
            sX[k4 + 0][r] = v.x; sX[k4 + 1][r] = v.y;
            sX[k4 + 2][r] = v.z; sX[k4 + 3][r] = v.w;
        }
        // stage W tile
        for (int i = tid; i < KCC * 16; i += 256) {
            int k  = i / 16;
            int c4 = (i % 16) * 4;
            int c = col0 + c4;
            float4 v = make_float4(0.f, 0.f, 0.f, 0.f);
            if constexpr (DOUT == 64) {
                if (c < NT)
                    v = *(const float4*)&Wb[(size_t)(c >> 6) * DIN * DOUT +
                                            (size_t)(kc * KC + k) * DOUT + (c & 63)];
            } else {
                float tmp[4];
                #pragma unroll
                for (int q = 0; q < 4; q++) {
                    int cc = c + q;
                    tmp[q] = (cc < NT)
                        ? Wb[(size_t)(cc / DOUT) * DIN * DOUT +
                             (size_t)(kc * KC + k) * DOUT + (cc % DOUT)]
                        : 0.f;
                }
                v = make_float4(tmp[0], tmp[1], tmp[2], tmp[3]);
            }
            *(float4*)&sW[k][c4] = v;
        }
        __syncthreads();

        #pragma unroll
        for (int k = 0; k < KCC; k++) {
            float4 a = *(const float4*)&sX[k][ty * 4];
            float4 b = *(const float4*)&sW[k][tx * 4];
            acc[0][0] += a.x * b.x; acc[0][1] += a.x * b.y; acc[0][2] += a.x * b.z; acc[0][3] += a.x * b.w;
            acc[1][0] += a.y * b.x; acc[1][1] += a.y * b.y; acc[1][2] += a.y * b.z; acc[1][3] += a.y * b.w;
            acc[2][0] += a.z * b.x; acc[2][1] += a.z * b.y; acc[2][2] += a.z * b.z; acc[2][3] += a.z * b.w;
            acc[3][0] += a.w * b.x; acc[3][1] += a.w * b.y; acc[3][2] += a.w * b.z; acc[3][3] += a.w * b.w;
        }
        __syncthreads();
    }

    #pragma unroll
    for (int r = 0; r < 4; r++) {
        int n = row0 + ty * 4 + r;
        if (n >= N_NODES) continue;
        int c = col0 + tx * 4;
        if constexpr ((NT & 63) == 0) {
            *(float4*)&out[(size_t)n * NT + c] =
                make_float4(acc[r][0], acc[r][1], acc[r][2], acc[r][3]);
        } else {
            #pragma unroll
            for (int q = 0; q < 4; q++)
                if (c + q < NT) out[(size_t)n * NT + c + q] = acc[r][q];
        }
    }
}

// ---------------- per-node concat GEMM for tiny layers ----------------------
template<int DIN, int K, int DOUT>
__global__ void __launch_bounds__(256)
k_gemm_node(const float* __restrict__ T, const float* __restrict__ Wb,
            float* __restrict__ out) {
    constexpr int NT = K * DOUT;
    __shared__ float sWt[DIN * NT];   // sWt[i*NT + k*DOUT + j]
    for (int idx = threadIdx.x; idx < K * DIN * DOUT; idx += blockDim.x) {
        int k = idx / (DIN * DOUT);
        int rem = idx - k * DIN * DOUT;
        int i = rem / DOUT, j = rem - i * DOUT;
        sWt[i * NT + k * DOUT + j] = Wb[idx];
    }
    __syncthreads();
    int n = blockIdx.x * blockDim.x + threadIdx.x;
    if (n >= N_NODES) return;
    float x[DIN];
    #pragma unroll
    for (int i = 0; i < DIN; i++) x[i] = __ldg(&T[(size_t)n * DIN + i]);
    float acc[NT];
    #pragma unroll
    for (int c = 0; c < NT; c++) acc[c] = 0.f;
    #pragma unroll
    for (int i = 0; i < DIN; i++) {
        float xi = x[i];
        #pragma unroll
        for (int c = 0; c < NT; c++) acc[c] += xi * sWt[i * NT + c];
    }
    #pragma unroll
    for (int c = 0; c < NT; c++) out[(size_t)n * NT + c] = acc[c];
}

// ---------------- fused CSR prop + Clenshaw combine + epilogue --------------
// out[n] = xw[n] - sub[n] + wscale * sum_j w_j * tin[src_j]
// mode 0: plain write; mode 1: +bias; mode 2: +bias, BN, ReLU
template<int LANES, int VEC>
__global__ void __launch_bounds__(256)
k_prop2(const int* __restrict__ rowptr, const int* __restrict__ csrc,
        const float* __restrict__ cw,
        const float* __restrict__ tin, int tin_stride,
        const float* __restrict__ xw, int xw_stride,
        const float* __restrict__ sub, int sub_stride,
        float* __restrict__ outp, float wscale, int mode,
        const float* __restrict__ bias,
        const float* __restrict__ bng, const float* __restrict__ bnb,
        const float* __restrict__ bnm, const float* __restrict__ bnv) {
    long long idx = (long long)blockIdx.x * blockDim.x + threadIdx.x;
    int n = (int)(idx / LANES);
    int l = (int)(idx - (long long)n * LANES);
    if (n >= N_NODES) return;
    int j0 = rowptr[n], j1 = rowptr[n + 1];
    constexpr int DIM = LANES * VEC;
    float acc[VEC];
    #pragma unroll
    for (int v = 0; v < VEC; v++) acc[v] = 0.f;
    for (int j = j0; j < j1; j++) {
        int s   = __ldg(&csrc[j]);
        float w = __ldg(&cw[j]);
        const float* tp = tin + (size_t)s * tin_stride + l * VEC;
        if constexpr (VEC == 4) {
            acc[0] += w * tp[0]; acc[1] += w * tp[1];
            acc[2] += w * tp[2]; acc[3] += w * tp[3];
        } else if constexpr (VEC == 2) {
            acc[0] += w * tp[0]; acc[1] += w * tp[1];
        } else {
            acc[0] += w * tp[0];
        }
    }
    const float* xp = xw + (size_t)n * xw_stride + l * VEC;
    const float* sp = sub ? sub + (size_t)n * sub_stride + l * VEC : nullptr;
    float* op = outp + (size_t)n * DIM + l * VEC;
    #pragma unroll
    for (int v = 0; v < VEC; v++) {
        float z = xp[v] + wscale * acc[v];
        if (sp) z -= sp[v];
        if (mode >= 1) {
            int jch = l * VEC + v;
            z += bias[jch];
            if (mode == 2) {
                z = (z - bnm[jch]) * (bng[jch] * rsqrtf(bnv[jch] + 1e-5f)) + bnb[jch];
                z = fmaxf(z, 0.f);
            }
        }
        op[v] = z;
    }
}

// ---------------- host-side layer driver (Clenshaw, concat GEMM) ------------
template<int DIN, int DOUT, int K, int LANES, int VEC>
static void cheb_layer(const float* input, const float* Wb, const float* bias,
                       const float* bng, const float* bnb, const float* bnm, const float* bnv,
                       float* out, int final_mode,
                       const int* rowptr, const int* csrc, const float* cw,
                       float* xw, float* r0, float* r1, float* r2) {
    static_assert(LANES * VEC == DOUT, "bad LANES/VEC");
    constexpr int NT = K * DOUT;

    // one concat GEMM for all K weight slices (slice k at cols [k*DOUT, (k+1)*DOUT))
    if constexpr (DIN >= 64) {
        dim3 grid((N_NODES + 63) / 64, (NT + 63) / 64);
        k_gemm_big<DIN, NT, DOUT><<<grid, 256>>>(input, Wb, xw);
    } else {
        k_gemm_node<DIN, K, DOUT><<<(N_NODES + 255) / 256, 256>>>(input, Wb, xw);
    }

    long long ptot = (long long)N_NODES * LANES;
    int pgrid = (int)((ptot + 255) / 256);

    // Clenshaw: b_{K-1} = XW_{K-1} (alias into xw)
    const float* b1p = xw + (size_t)(K - 1) * DOUT; int b1s = NT;
    const float* b2p = nullptr;                     int b2s = 0;
    float* rot[3] = {r0, r1, r2};
    int nx = 0;
    for (int k = K - 2; k >= 1; k--) {
        float* t = rot[nx];
        nx = (nx + 1) % 3;
        k_prop2<LANES, VEC><<<pgrid, 256>>>(rowptr, csrc, cw,
            b1p, b1s, xw + (size_t)k * DOUT, NT, b2p, b2s,
            t, 2.f, 0, nullptr, nullptr, nullptr, nullptr, nullptr);
        b2p = b1p; b2s = b1s;
        b1p = t;   b1s = DOUT;
    }
    // final: out = XW_0 - b_2 + L b_1, then epilogue
    k_prop2<LANES, VEC><<<pgrid, 256>>>(rowptr, csrc, cw,
        b1p, b1s, xw, NT, b2p, b2s,
        out, 1.f, final_mode, bias, bng, bnb, bnm, bnv);
}

extern "C" void kernel_launch(void* const* d_in, const int* in_sizes, int n_in,
                              void* d_out, int out_size) {
    const float* x   = (const float*)d_in[0];
    const int*   ei  = (const int*)d_in[1];
    const int*   src = ei;
    const int*   dst = ei + N_EDGES;
    const float* W1 = (const float*)d_in[2];  const float* b1 = (const float*)d_in[3];
    const float* W2 = (const float*)d_in[4];  const float* b2 = (const float*)d_in[5];
    const float* W3 = (const float*)d_in[6];  const float* b3 = (const float*)d_in[7];
    const float* W4 = (const float*)d_in[8];  const float* b4 = (const float*)d_in[9];
    const float* bn1g = (const float*)d_in[10]; const float* bn1b = (const float*)d_in[11];
    const float* bn1m = (const float*)d_in[12]; const float* bn1v = (const float*)d_in[13];
    const float* bn2g = (const float*)d_in[14]; const float* bn2b = (const float*)d_in[15];
    const float* bn2m = (const float*)d_in[16]; const float* bn2v = (const float*)d_in[17];
    const float* bn3g = (const float*)d_in[18]; const float* bn3b = (const float*)d_in[19];
    const float* bn3m = (const float*)d_in[20]; const float* bn3v = (const float*)d_in[21];

    int *degi, *rowptr, *cursor, *partial, *csrc;
    float *dinv, *cw, *xw, *bufA, *bufB, *bufC, *h;
    cudaGetSymbolAddress((void**)&degi,   g_degi);
    cudaGetSymbolAddress((void**)&dinv,   g_dinv);
    cudaGetSymbolAddress((void**)&rowptr, g_rowptr);
    cudaGetSymbolAddress((void**)&cursor, g_cursor);
    cudaGetSymbolAddress((void**)&partial,g_partial);
    cudaGetSymbolAddress((void**)&csrc,   g_csrc);
    cudaGetSymbolAddress((void**)&cw,     g_cw);
    cudaGetSymbolAddress((void**)&xw,     g_xw);
    cudaGetSymbolAddress((void**)&bufA,   g_bufA);
    cudaGetSymbolAddress((void**)&bufB,   g_bufB);
    cudaGetSymbolAddress((void**)&bufC,   g_bufC);
    cudaGetSymbolAddress((void**)&h,      g_h);

    // ---- CSR build ----
    k_zeroi<<<(N_NODES + 255) / 256, 256>>>(degi, N_NODES);
    k_zeroi<<<(N_NODES + 255) / 256, 256>>>(cursor, N_NODES);
    k_hist  <<<(N_EDGES + 255) / 256, 256>>>(dst, degi);
    k_dinv_k<<<(N_NODES + 255) / 256, 256>>>(degi, dinv);
    k_scan1 <<<NBLK, SCAN_B>>>(degi, rowptr, partial);
    k_scan2 <<<1, 128>>>(partial);
    k_scan3 <<<(N_NODES + 255) / 256, 256>>>(rowptr, partial);
    k_fill  <<<(N_EDGES + 255) / 256, 256>>>(src, dst, dinv, rowptr, cursor, csrc, cw);

    // layer 1: 128 -> 64, K=8, BN+ReLU
    cheb_layer<128, 64, 8, 16, 4>(x, W1, b1, bn1g, bn1b, bn1m, bn1v, h, 2,
                                  rowptr, csrc, cw, xw, bufA, bufB, bufC);
    // layer 2: 64 -> 18, K=6, BN+ReLU
    cheb_layer<64, 18, 6, 9, 2>(h, W2, b2, bn2g, bn2b, bn2m, bn2v, h, 2,
                                rowptr, csrc, cw, xw, bufA, bufB, bufC);
    // layer 3: 18 -> 9, K=4, BN+ReLU
    cheb_layer<18, 9, 4, 9, 1>(h, W3, b3, bn3g, bn3b, bn3m, bn3v, h, 2,
                               rowptr, csrc, cw, xw, bufA, bufB, bufC);
    // layer 4: 9 -> 10, K=4, bias only, write d_out
    cheb_layer<9, 10, 4, 5, 2>(h, W4, b4, nullptr, nullptr, nullptr, nullptr,
                               (float*)d_out, 1,
                               rowptr, csrc, cw, xw, bufA, bufB, bufC);
}

// round 8
// speedup vs baseline: 3.0387x; 1.1250x over previous
#include <cuda_runtime.h>
#include <cuda_bf16.h>
#include <mma.h>
using namespace nvcuda;

#define N_NODES 100000
#define M_PAD   100032            // 1563 * 64
#define N_EDGES 1600000
#define SCAN_B  1024
#define NBLK    ((N_NODES + SCAN_B - 1) / SCAN_B)   // 98

// ---------------- scratch (device globals; no runtime allocation) ----------
__device__ int   g_degi  [N_NODES];
__device__ float g_dinv  [N_NODES];
__device__ int   g_rowptr[N_NODES + 1];
__device__ int   g_cursor[N_NODES];
__device__ int   g_partial[128];
__device__ int   g_csrc[N_EDGES];
__device__ float g_cw  [N_EDGES];
__device__ float g_xw  [(size_t)M_PAD * 512];     // concat GEMM output (padded rows)
__device__ float g_bufA[(size_t)N_NODES * 64];
__device__ float g_bufB[(size_t)N_NODES * 64];
__device__ float g_bufC[(size_t)N_NODES * 64];
__device__ float g_h   [(size_t)N_NODES * 64];
__device__ __nv_bfloat16 g_xhi[(size_t)N_NODES * 128];
__device__ __nv_bfloat16 g_xlo[(size_t)N_NODES * 128];
__device__ __nv_bfloat16 g_whi[128 * 512];
__device__ __nv_bfloat16 g_wlo[128 * 512];

// ---------------- small helpers ---------------------------------------------
__global__ void k_zeroi(int* __restrict__ p, int n) {
    int i = blockIdx.x * blockDim.x + threadIdx.x;
    if (i < n) p[i] = 0;
}

// ---------------- CSR build --------------------------------------------------
__global__ void k_hist(const int* __restrict__ dst, int* __restrict__ degi) {
    int e = blockIdx.x * blockDim.x + threadIdx.x;
    if (e < N_EDGES) atomicAdd(&degi[dst[e]], 1);
}

__global__ void k_dinv_k(const int* __restrict__ degi, float* __restrict__ dinv) {
    int i = blockIdx.x * blockDim.x + threadIdx.x;
    if (i < N_NODES) {
        int d = degi[i];
        dinv[i] = (d > 0) ? rsqrtf((float)d) : 0.f;
    }
}

__global__ void k_scan1(const int* __restrict__ degi, int* __restrict__ rowptr,
                        int* __restrict__ partial) {
    __shared__ int s[SCAN_B];
    int t = threadIdx.x;
    int i = blockIdx.x * SCAN_B + t;
    int v = (i < N_NODES) ? degi[i] : 0;
    s[t] = v;
    __syncthreads();
    for (int off = 1; off < SCAN_B; off <<= 1) {
        int x = (t >= off) ? s[t - off] : 0;
        __syncthreads();
        s[t] += x;
        __syncthreads();
    }
    if (i < N_NODES) rowptr[i + 1] = s[t];
    if (t == SCAN_B - 1) partial[blockIdx.x] = s[t];
}

__global__ void k_scan2(int* __restrict__ partial) {
    __shared__ int s[128];
    int t = threadIdx.x;
    int v = (t < NBLK) ? partial[t] : 0;
    s[t] = v;
    __syncthreads();
    for (int off = 1; off < 128; off <<= 1) {
        int x = (t >= off) ? s[t - off] : 0;
        __syncthreads();
        s[t] += x;
        __syncthreads();
    }
    if (t < NBLK) partial[t] = s[t] - v;   // exclusive
}

__global__ void k_scan3(int* __restrict__ rowptr, const int* __restrict__ partial) {
    int i = blockIdx.x * blockDim.x + threadIdx.x;
    if (i < N_NODES) rowptr[i + 1] += partial[i / SCAN_B];
    if (i == 0) rowptr[0] = 0;
}

__global__ void k_fill(const int* __restrict__ src, const int* __restrict__ dst,
                       const float* __restrict__ dinv, const int* __restrict__ rowptr,
                       int* __restrict__ cursor, int* __restrict__ csrc,
                       float* __restrict__ cw) {
    int e = blockIdx.x * blockDim.x + threadIdx.x;
    if (e >= N_EDGES) return;
    int s = src[e], d = dst[e];
    int pos = atomicAdd(&cursor[d], 1);
    int idx = rowptr[d] + pos;
    csrc[idx] = s;
    cw[idx]   = -dinv[s] * dinv[d];
}

// ---------------- bf16 hi/lo split ------------------------------------------
template<int DIN>
__global__ void __launch_bounds__(256)
k_split(const float* __restrict__ in, __nv_bfloat16* __restrict__ hi,
        __nv_bfloat16* __restrict__ lo) {
    int idx = blockIdx.x * blockDim.x + threadIdx.x;
    if (idx >= N_NODES * DIN / 4) return;
    float4 v = ((const float4*)in)[idx];
    float vs[4] = {v.x, v.y, v.z, v.w};
    __nv_bfloat16 h[4], l[4];
    #pragma unroll
    for (int q = 0; q < 4; q++) {
        h[q] = __float2bfloat16(vs[q]);
        l[q] = __float2bfloat16(vs[q] - __bfloat162float(h[q]));
    }
    __nv_bfloat162* hp = (__nv_bfloat162*)(hi + (size_t)idx * 4);
    __nv_bfloat162* lp = (__nv_bfloat162*)(lo + (size_t)idx * 4);
    hp[0] = __nv_bfloat162(h[0], h[1]); hp[1] = __nv_bfloat162(h[2], h[3]);
    lp[0] = __nv_bfloat162(l[0], l[1]); lp[1] = __nv_bfloat162(l[2], l[3]);
}

// W concat split: wsp[i][c] (c = k*DOUT + j for c < K*DOUT, 0 padded to NTP)
template<int DIN, int K, int DOUT, int NTP>
__global__ void k_wsplit(const float* __restrict__ Wb,
                         __nv_bfloat16* __restrict__ whi,
                         __nv_bfloat16* __restrict__ wlo) {
    int idx = blockIdx.x * blockDim.x + threadIdx.x;
    if (idx >= DIN * NTP) return;
    int i = idx / NTP, c = idx - i * NTP;
    float v = 0.f;
    if (c < K * DOUT)
        v = Wb[(size_t)(c / DOUT) * DIN * DOUT + (size_t)i * DOUT + (c % DOUT)];
    __nv_bfloat16 h = __float2bfloat16(v);
    whi[idx] = h;
    wlo[idx] = __float2bfloat16(v - __bfloat162float(h));
}

// ---------------- wmma split-bf16 GEMM: out[M_PAD][NTP] = X @ Wcat ----------
// 64x64 block tile, 8 warps (4m x 2n), K chunk 64.
// out = Xhi*Whi + Xhi*Wlo + Xlo*Whi  (fp32 accum; lo*lo dropped)
template<int DIN, int NTP>
__global__ void __launch_bounds__(256)
k_gemm_wmma(const __nv_bfloat16* __restrict__ Ahi, const __nv_bfloat16* __restrict__ Alo,
            const __nv_bfloat16* __restrict__ Whi, const __nv_bfloat16* __restrict__ Wlo,
            float* __restrict__ out) {
    constexpr int LDS_ = 72;   // row stride (bf16): 144 B, 16B-aligned
    __shared__ __align__(16) __nv_bfloat16 sAh[64][LDS_], sAl[64][LDS_];
    __shared__ __align__(16) __nv_bfloat16 sBh[64][LDS_], sBl[64][LDS_];
    int tid = threadIdx.x;
    int wid = tid >> 5;
    int m0 = blockIdx.x * 64;
    int n0 = blockIdx.y * 64;
    int wm = (wid & 3) * 16;      // warp row offset
    int wn = (wid >> 2) * 32;     // warp col offset

    wmma::fragment<wmma::accumulator, 16, 16, 16, float> c0, c1;
    wmma::fill_fragment(c0, 0.f);
    wmma::fill_fragment(c1, 0.f);

    for (int k0 = 0; k0 < DIN; k0 += 64) {
        // stage A (64 rows x 64 k): 4 threads/row, 16 bf16 each = 2 x uint4
        {
            int r = tid >> 2, cc = (tid & 3) * 16;
            int n = m0 + r;
            uint4 vh0 = make_uint4(0u,0u,0u,0u), vh1 = vh0, vl0 = vh0, vl1 = vh0;
            if (n < N_NODES) {
                const __nv_bfloat16* ph = &Ahi[(size_t)n * DIN + k0 + cc];
                const __nv_bfloat16* pl = &Alo[(size_t)n * DIN + k0 + cc];
                vh0 = *(const uint4*)(ph);     vh1 = *(const uint4*)(ph + 8);
                vl0 = *(const uint4*)(pl);     vl1 = *(const uint4*)(pl + 8);
            }
            *(uint4*)&sAh[r][cc]     = vh0;  *(uint4*)&sAh[r][cc + 8] = vh1;
            *(uint4*)&sAl[r][cc]     = vl0;  *(uint4*)&sAl[r][cc + 8] = vl1;
        }
        // stage B row-major: sB[k][n] = W[(k0+k)][n0+n], vectorized
        for (int i = tid; i < 64 * 8; i += 256) {
            int k = i >> 3, n8 = (i & 7) * 8;
            *(uint4*)&sBh[k][n8] = *(const uint4*)&Whi[(size_t)(k0 + k) * NTP + n0 + n8];
            *(uint4*)&sBl[k][n8] = *(const uint4*)&Wlo[(size_t)(k0 + k) * NTP + n0 + n8];
        }
        __syncthreads();

        #pragma unroll
        for (int kk = 0; kk < 64; kk += 16) {
            wmma::fragment<wmma::matrix_a, 16, 16, 16, __nv_bfloat16, wmma::row_major> ah, al;
            wmma::load_matrix_sync(ah, &sAh[wm][kk], LDS_);
            wmma::load_matrix_sync(al, &sAl[wm][kk], LDS_);
            {
                wmma::fragment<wmma::matrix_b, 16, 16, 16, __nv_bfloat16, wmma::row_major> bh, bl;
                wmma::load_matrix_sync(bh, &sBh[kk][wn], LDS_);
                wmma::load_matrix_sync(bl, &sBl[kk][wn], LDS_);
                wmma::mma_sync(c0, ah, bh, c0);
                wmma::mma_sync(c0, ah, bl, c0);
                wmma::mma_sync(c0, al, bh, c0);
            }
            {
                wmma::fragment<wmma::matrix_b, 16, 16, 16, __nv_bfloat16, wmma::row_major> bh, bl;
                wmma::load_matrix_sync(bh, &sBh[kk][wn + 16], LDS_);
                wmma::load_matrix_sync(bl, &sBl[kk][wn + 16], LDS_);
                wmma::mma_sync(c1, ah, bh, c1);
                wmma::mma_sync(c1, ah, bl, c1);
                wmma::mma_sync(c1, al, bh, c1);
            }
        }
        __syncthreads();
    }

    // out rows padded to M_PAD — no guard needed
    wmma::store_matrix_sync(&out[(size_t)(m0 + wm) * NTP + n0 + wn],      c0, NTP, wmma::mem_row_major);
    wmma::store_matrix_sync(&out[(size_t)(m0 + wm) * NTP + n0 + wn + 16], c1, NTP, wmma::mem_row_major);
}

// ---------------- per-node concat GEMM for tiny layers ----------------------
template<int DIN, int K, int DOUT>
__global__ void __launch_bounds__(256)
k_gemm_node(const float* __restrict__ T, const float* __restrict__ Wb,
            float* __restrict__ out) {
    constexpr int NT = K * DOUT;
    __shared__ float sWt[DIN * NT];
    for (int idx = threadIdx.x; idx < K * DIN * DOUT; idx += blockDim.x) {
        int k = idx / (DIN * DOUT);
        int rem = idx - k * DIN * DOUT;
        int i = rem / DOUT, j = rem - i * DOUT;
        sWt[i * NT + k * DOUT + j] = Wb[idx];
    }
    __syncthreads();
    int n = blockIdx.x * blockDim.x + threadIdx.x;
    if (n >= N_NODES) return;
    float x[DIN];
    #pragma unroll
    for (int i = 0; i < DIN; i++) x[i] = __ldg(&T[(size_t)n * DIN + i]);
    float acc[NT];
    #pragma unroll
    for (int c = 0; c < NT; c++) acc[c] = 0.f;
    #pragma unroll
    for (int i = 0; i < DIN; i++) {
        float xi = x[i];
        #pragma unroll
        for (int c = 0; c < NT; c++) acc[c] += xi * sWt[i * NT + c];
    }
    #pragma unroll
    for (int c = 0; c < NT; c++) out[(size_t)n * NT + c] = acc[c];
}

// ---------------- fused CSR prop + Clenshaw combine + epilogue --------------
template<int LANES, int VEC>
__global__ void __launch_bounds__(256)
k_prop2(const int* __restrict__ rowptr, const int* __restrict__ csrc,
        const float* __restrict__ cw,
        const float* __restrict__ tin, int tin_stride,
        const float* __restrict__ xw, int xw_stride,
        const float* __restrict__ sub, int sub_stride,
        float* __restrict__ outp, float wscale, int mode,
        const float* __restrict__ bias,
        const float* __restrict__ bng, const float* __restrict__ bnb,
        const float* __restrict__ bnm, const float* __restrict__ bnv) {
    long long idx = (long long)blockIdx.x * blockDim.x + threadIdx.x;
    int n = (int)(idx / LANES);
    int l = (int)(idx - (long long)n * LANES);
    if (n >= N_NODES) return;
    int j0 = rowptr[n], j1 = rowptr[n + 1];
    constexpr int DIM = LANES * VEC;
    float acc[VEC];
    #pragma unroll
    for (int v = 0; v < VEC; v++) acc[v] = 0.f;
    for (int j = j0; j < j1; j++) {
        int s   = __ldg(&csrc[j]);
        float w = __ldg(&cw[j]);
        const float* tp = tin + (size_t)s * tin_stride + l * VEC;
        if constexpr (VEC == 4) {
            acc[0] += w * tp[0]; acc[1] += w * tp[1];
            acc[2] += w * tp[2]; acc[3] += w * tp[3];
        } else if constexpr (VEC == 2) {
            acc[0] += w * tp[0]; acc[1] += w * tp[1];
        } else {
            acc[0] += w * tp[0];
        }
    }
    const float* xp = xw + (size_t)n * xw_stride + l * VEC;
    const float* sp = sub ? sub + (size_t)n * sub_stride + l * VEC : nullptr;
    float* op = outp + (size_t)n * DIM + l * VEC;
    #pragma unroll
    for (int v = 0; v < VEC; v++) {
        float z = xp[v] + wscale * acc[v];
        if (sp) z -= sp[v];
        if (mode >= 1) {
            int jch = l * VEC + v;
            z += bias[jch];
            if (mode == 2) {
                z = (z - bnm[jch]) * (bng[jch] * rsqrtf(bnv[jch] + 1e-5f)) + bnb[jch];
                z = fmaxf(z, 0.f);
            }
        }
        op[v] = z;
    }
}

// ---------------- host-side layer driver (Clenshaw, tensor GEMM) ------------
template<int DIN, int DOUT, int K, int NTP, int LANES, int VEC>
static void cheb_layer(const float* input, const float* Wb, const float* bias,
                       const float* bng, const float* bnb, const float* bnm, const float* bnv,
                       float* out, int final_mode,
                       const int* rowptr, const int* csrc, const float* cw,
                       float* xw, float* r0, float* r1, float* r2,
                       __nv_bfloat16* xhi, __nv_bfloat16* xlo,
                       __nv_bfloat16* whi, __nv_bfloat16* wlo) {
    static_assert(LANES * VEC == DOUT, "bad LANES/VEC");

    if constexpr (DIN >= 64) {
        k_split<DIN><<<(N_NODES * DIN / 4 + 255) / 256, 256>>>(input, xhi, xlo);
        k_wsplit<DIN, K, DOUT, NTP><<<(DIN * NTP + 255) / 256, 256>>>(Wb, whi, wlo);
        dim3 grid((N_NODES + 63) / 64, NTP / 64);
        k_gemm_wmma<DIN, NTP><<<grid, 256>>>(xhi, xlo, whi, wlo, xw);
    } else {
        k_gemm_node<DIN, K, DOUT><<<(N_NODES + 255) / 256, 256>>>(input, Wb, xw);
    }
    constexpr int XWS = (DIN >= 64) ? NTP : K * DOUT;   // storage stride of xw

    long long ptot = (long long)N_NODES * LANES;
    int pgrid = (int)((ptot + 255) / 256);

    // Clenshaw: b_{K-1} = XW_{K-1} (alias into xw)
    const float* b1p = xw + (size_t)(K - 1) * DOUT; int b1s = XWS;
    const float* b2p = nullptr;                     int b2s = 0;
    float* rot[3] = {r0, r1, r2};
    int nx = 0;
    for (int k = K - 2; k >= 1; k--) {
        float* t = rot[nx];
        nx = (nx + 1) % 3;
        k_prop2<LANES, VEC><<<pgrid, 256>>>(rowptr, csrc, cw,
            b1p, b1s, xw + (size_t)k * DOUT, XWS, b2p, b2s,
            t, 2.f, 0, nullptr, nullptr, nullptr, nullptr, nullptr);
        b2p = b1p; b2s = b1s;
        b1p = t;   b1s = DOUT;
    }
    k_prop2<LANES, VEC><<<pgrid, 256>>>(rowptr, csrc, cw,
        b1p, b1s, xw, XWS, b2p, b2s,
        out, 1.f, final_mode, bias, bng, bnb, bnm, bnv);
}

extern "C" void kernel_launch(void* const* d_in, const int* in_sizes, int n_in,
                              void* d_out, int out_size) {
    const float* x   = (const float*)d_in[0];
    const int*   ei  = (const int*)d_in[1];
    const int*   src = ei;
    const int*   dst = ei + N_EDGES;
    const float* W1 = (const float*)d_in[2];  const float* b1 = (const float*)d_in[3];
    const float* W2 = (const float*)d_in[4];  const float* b2 = (const float*)d_in[5];
    const float* W3 = (const float*)d_in[6];  const float* b3 = (const float*)d_in[7];
    const float* W4 = (const float*)d_in[8];  const float* b4 = (const float*)d_in[9];
    const float* bn1g = (const float*)d_in[10]; const float* bn1b = (const float*)d_in[11];
    const float* bn1m = (const float*)d_in[12]; const float* bn1v = (const float*)d_in[13];
    const float* bn2g = (const float*)d_in[14]; const float* bn2b = (const float*)d_in[15];
    const float* bn2m = (const float*)d_in[16]; const float* bn2v = (const float*)d_in[17];
    const float* bn3g = (const float*)d_in[18]; const float* bn3b = (const float*)d_in[19];
    const float* bn3m = (const float*)d_in[20]; const float* bn3v = (const float*)d_in[21];

    int *degi, *rowptr, *cursor, *partial, *csrc;
    float *dinv, *cw, *xw, *bufA, *bufB, *bufC, *h;
    __nv_bfloat16 *xhi, *xlo, *whi, *wlo;
    cudaGetSymbolAddress((void**)&degi,   g_degi);
    cudaGetSymbolAddress((void**)&dinv,   g_dinv);
    cudaGetSymbolAddress((void**)&rowptr, g_rowptr);
    cudaGetSymbolAddress((void**)&cursor, g_cursor);
    cudaGetSymbolAddress((void**)&partial,g_partial);
    cudaGetSymbolAddress((void**)&csrc,   g_csrc);
    cudaGetSymbolAddress((void**)&cw,     g_cw);
    cudaGetSymbolAddress((void**)&xw,     g_xw);
    cudaGetSymbolAddress((void**)&bufA,   g_bufA);
    cudaGetSymbolAddress((void**)&bufB,   g_bufB);
    cudaGetSymbolAddress((void**)&bufC,   g_bufC);
    cudaGetSymbolAddress((void**)&h,      g_h);
    cudaGetSymbolAddress((void**)&xhi,    g_xhi);
    cudaGetSymbolAddress((void**)&xlo,    g_xlo);
    cudaGetSymbolAddress((void**)&whi,    g_whi);
    cudaGetSymbolAddress((void**)&wlo,    g_wlo);

    // ---- CSR build ----
    k_zeroi<<<(N_NODES + 255) / 256, 256>>>(degi, N_NODES);
    k_zeroi<<<(N_NODES + 255) / 256, 256>>>(cursor, N_NODES);
    k_hist  <<<(N_EDGES + 255) / 256, 256>>>(dst, degi);
    k_dinv_k<<<(N_NODES + 255) / 256, 256>>>(degi, dinv);
    k_scan1 <<<NBLK, SCAN_B>>>(degi, rowptr, partial);
    k_scan2 <<<1, 128>>>(partial);
    k_scan3 <<<(N_NODES + 255) / 256, 256>>>(rowptr, partial);
    k_fill  <<<(N_EDGES + 255) / 256, 256>>>(src, dst, dinv, rowptr, cursor, csrc, cw);

    // layer 1: 128 -> 64, K=8, BN+ReLU (tensor GEMM, NTP=512)
    cheb_layer<128, 64, 8, 512, 16, 4>(x, W1, b1, bn1g, bn1b, bn1m, bn1v, h, 2,
                                       rowptr, csrc, cw, xw, bufA, bufB, bufC,
                                       xhi, xlo, whi, wlo);
    // layer 2: 64 -> 18, K=6, BN+ReLU (tensor GEMM, NT=108 padded to 128)
    cheb_layer<64, 18, 6, 128, 9, 2>(h, W2, b2, bn2g, bn2b, bn2m, bn2v, h, 2,
                                     rowptr, csrc, cw, xw, bufA, bufB, bufC,
                                     xhi, xlo, whi, wlo);
    // layer 3: 18 -> 9, K=4, BN+ReLU
    cheb_layer<18, 9, 4, 0, 9, 1>(h, W3, b3, bn3g, bn3b, bn3m, bn3v, h, 2,
                                  rowptr, csrc, cw, xw, bufA, bufB, bufC,
                                  xhi, xlo, whi, wlo);
    // layer 4: 9 -> 10, K=4, bias only, write d_out
    cheb_layer<9, 10, 4, 0, 5, 2>(h, W4, b4, nullptr, nullptr, nullptr, nullptr,
                                  (float*)d_out, 1,
                                  rowptr, csrc, cw, xw, bufA, bufB, bufC,
                                  xhi, xlo, whi, wlo);
}

// round 13
// speedup vs baseline: 3.8632x; 1.2713x over previous
#include <cuda_runtime.h>
#include <cuda_bf16.h>
#include <mma.h>
using namespace nvcuda;

#define N_NODES 100000
#define M_PAD   100032            // 1563 * 64
#define N_EDGES 1600000
#define SCAN_B  1024
#define NBLK    ((N_NODES + SCAN_B - 1) / SCAN_B)   // 98

// ---------------- scratch (device globals; no runtime allocation) ----------
__device__ int   g_degi  [N_NODES];
__device__ float g_dinv  [N_NODES];
__device__ int   g_rowptr[N_NODES + 1];
__device__ int   g_cursor[N_NODES];
__device__ int   g_partial[128];
__device__ int   g_csrc[N_EDGES];
__device__ float g_cw  [N_EDGES];
__device__ float g_xw  [(size_t)M_PAD * 512];     // concat GEMM output (padded rows)
__device__ float g_bufA[(size_t)N_NODES * 64];
__device__ float g_bufB[(size_t)N_NODES * 64];
__device__ float g_bufC[(size_t)N_NODES * 64];
__device__ float g_h   [(size_t)N_NODES * 64];
__device__ __nv_bfloat16 g_xhi[(size_t)N_NODES * 128];
__device__ __nv_bfloat16 g_xlo[(size_t)N_NODES * 128];
__device__ __nv_bfloat16 g_whi[128 * 512];
__device__ __nv_bfloat16 g_wlo[128 * 512];

// ---------------- small helpers ---------------------------------------------
__global__ void k_zeroi(int* __restrict__ p, int n) {
    int i = blockIdx.x * blockDim.x + threadIdx.x;
    if (i < n) p[i] = 0;
}

// ---------------- CSR build --------------------------------------------------
__global__ void k_hist(const int* __restrict__ dst, int* __restrict__ degi) {
    int e = blockIdx.x * blockDim.x + threadIdx.x;
    if (e < N_EDGES) atomicAdd(&degi[dst[e]], 1);
}

__global__ void k_dinv_k(const int* __restrict__ degi, float* __restrict__ dinv) {
    int i = blockIdx.x * blockDim.x + threadIdx.x;
    if (i < N_NODES) {
        int d = degi[i];
        dinv[i] = (d > 0) ? rsqrtf((float)d) : 0.f;
    }
}

__global__ void k_scan1(const int* __restrict__ degi, int* __restrict__ rowptr,
                        int* __restrict__ partial) {
    __shared__ int s[SCAN_B];
    int t = threadIdx.x;
    int i = blockIdx.x * SCAN_B + t;
    int v = (i < N_NODES) ? degi[i] : 0;
    s[t] = v;
    __syncthreads();
    for (int off = 1; off < SCAN_B; off <<= 1) {
        int x = (t >= off) ? s[t - off] : 0;
        __syncthreads();
        s[t] += x;
        __syncthreads();
    }
    if (i < N_NODES) rowptr[i + 1] = s[t];
    if (t == SCAN_B - 1) partial[blockIdx.x] = s[t];
}

__global__ void k_scan2(int* __restrict__ partial) {
    __shared__ int s[128];
    int t = threadIdx.x;
    int v = (t < NBLK) ? partial[t] : 0;
    s[t] = v;
    __syncthreads();
    for (int off = 1; off < 128; off <<= 1) {
        int x = (t >= off) ? s[t - off] : 0;
        __syncthreads();
        s[t] += x;
        __syncthreads();
    }
    if (t < NBLK) partial[t] = s[t] - v;   // exclusive
}

__global__ void k_scan3(int* __restrict__ rowptr, const int* __restrict__ partial) {
    int i = blockIdx.x * blockDim.x + threadIdx.x;
    if (i < N_NODES) rowptr[i + 1] += partial[i / SCAN_B];
    if (i == 0) rowptr[0] = 0;
}

__global__ void k_fill(const int* __restrict__ src, const int* __restrict__ dst,
                       const float* __restrict__ dinv, const int* __restrict__ rowptr,
                       int* __restrict__ cursor, int* __restrict__ csrc,
                       float* __restrict__ cw) {
    int e = blockIdx.x * blockDim.x + threadIdx.x;
    if (e >= N_EDGES) return;
    int s = src[e], d = dst[e];
    int pos = atomicAdd(&cursor[d], 1);
    int idx = rowptr[d] + pos;
    csrc[idx] = s;
    cw[idx]   = -dinv[s] * dinv[d];
}

// ---------------- bf16 hi/lo split ------------------------------------------
template<int DIN>
__global__ void __launch_bounds__(256)
k_split(const float* __restrict__ in, __nv_bfloat16* __restrict__ hi,
        __nv_bfloat16* __restrict__ lo) {
    int idx = blockIdx.x * blockDim.x + threadIdx.x;
    if (idx >= N_NODES * DIN / 4) return;
    float4 v = ((const float4*)in)[idx];
    float vs[4] = {v.x, v.y, v.z, v.w};
    __nv_bfloat16 h[4], l[4];
    #pragma unroll
    for (int q = 0; q < 4; q++) {
        h[q] = __float2bfloat16(vs[q]);
        l[q] = __float2bfloat16(vs[q] - __bfloat162float(h[q]));
    }
    __nv_bfloat162* hp = (__nv_bfloat162*)(hi + (size_t)idx * 4);
    __nv_bfloat162* lp = (__nv_bfloat162*)(lo + (size_t)idx * 4);
    hp[0] = __nv_bfloat162(h[0], h[1]); hp[1] = __nv_bfloat162(h[2], h[3]);
    lp[0] = __nv_bfloat162(l[0], l[1]); lp[1] = __nv_bfloat162(l[2], l[3]);
}

// W concat split: wsp[i][c] (c = k*DOUT + j for c < K*DOUT, 0 padded to NTP)
template<int DIN, int K, int DOUT, int NTP>
__global__ void k_wsplit(const float* __restrict__ Wb,
                         __nv_bfloat16* __restrict__ whi,
                         __nv_bfloat16* __restrict__ wlo) {
    int idx = blockIdx.x * blockDim.x + threadIdx.x;
    if (idx >= DIN * NTP) return;
    int i = idx / NTP, c = idx - i * NTP;
    float v = 0.f;
    if (c < K * DOUT)
        v = Wb[(size_t)(c / DOUT) * DIN * DOUT + (size_t)i * DOUT + (c % DOUT)];
    __nv_bfloat16 h = __float2bfloat16(v);
    whi[idx] = h;
    wlo[idx] = __float2bfloat16(v - __bfloat162float(h));
}

// ---------------- wmma split-bf16 GEMM: out[M_PAD][NTP] = X @ Wcat ----------
template<int DIN, int NTP>
__global__ void __launch_bounds__(256)
k_gemm_wmma(const __nv_bfloat16* __restrict__ Ahi, const __nv_bfloat16* __restrict__ Alo,
            const __nv_bfloat16* __restrict__ Whi, const __nv_bfloat16* __restrict__ Wlo,
            float* __restrict__ out) {
    constexpr int LDS_ = 72;
    __shared__ __align__(16) __nv_bfloat16 sAh[64][LDS_], sAl[64][LDS_];
    __shared__ __align__(16) __nv_bfloat16 sBh[64][LDS_], sBl[64][LDS_];
    int tid = threadIdx.x;
    int wid = tid >> 5;
    int m0 = blockIdx.x * 64;
    int n0 = blockIdx.y * 64;
    int wm = (wid & 3) * 16;
    int wn = (wid >> 2) * 32;

    wmma::fragment<wmma::accumulator, 16, 16, 16, float> c0, c1;
    wmma::fill_fragment(c0, 0.f);
    wmma::fill_fragment(c1, 0.f);

    for (int k0 = 0; k0 < DIN; k0 += 64) {
        {
            int r = tid >> 2, cc = (tid & 3) * 16;
            int n = m0 + r;
            uint4 vh0 = make_uint4(0u,0u,0u,0u), vh1 = vh0, vl0 = vh0, vl1 = vh0;
            if (n < N_NODES) {
                const __nv_bfloat16* ph = &Ahi[(size_t)n * DIN + k0 + cc];
                const __nv_bfloat16* pl = &Alo[(size_t)n * DIN + k0 + cc];
                vh0 = *(const uint4*)(ph);     vh1 = *(const uint4*)(ph + 8);
                vl0 = *(const uint4*)(pl);     vl1 = *(const uint4*)(pl + 8);
            }
            *(uint4*)&sAh[r][cc]     = vh0;  *(uint4*)&sAh[r][cc + 8] = vh1;
            *(uint4*)&sAl[r][cc]     = vl0;  *(uint4*)&sAl[r][cc + 8] = vl1;
        }
        for (int i = tid; i < 64 * 8; i += 256) {
            int k = i >> 3, n8 = (i & 7) * 8;
            *(uint4*)&sBh[k][n8] = *(const uint4*)&Whi[(size_t)(k0 + k) * NTP + n0 + n8];
            *(uint4*)&sBl[k][n8] = *(const uint4*)&Wlo[(size_t)(k0 + k) * NTP + n0 + n8];
        }
        __syncthreads();

        #pragma unroll
        for (int kk = 0; kk < 64; kk += 16) {
            wmma::fragment<wmma::matrix_a, 16, 16, 16, __nv_bfloat16, wmma::row_major> ah, al;
            wmma::load_matrix_sync(ah, &sAh[wm][kk], LDS_);
            wmma::load_matrix_sync(al, &sAl[wm][kk], LDS_);
            {
                wmma::fragment<wmma::matrix_b, 16, 16, 16, __nv_bfloat16, wmma::row_major> bh, bl;
                wmma::load_matrix_sync(bh, &sBh[kk][wn], LDS_);
                wmma::load_matrix_sync(bl, &sBl[kk][wn], LDS_);
                wmma::mma_sync(c0, ah, bh, c0);
                wmma::mma_sync(c0, ah, bl, c0);
                wmma::mma_sync(c0, al, bh, c0);
            }
            {
                wmma::fragment<wmma::matrix_b, 16, 16, 16, __nv_bfloat16, wmma::row_major> bh, bl;
                wmma::load_matrix_sync(bh, &sBh[kk][wn + 16], LDS_);
                wmma::load_matrix_sync(bl, &sBl[kk][wn + 16], LDS_);
                wmma::mma_sync(c1, ah, bh, c1);
                wmma::mma_sync(c1, ah, bl, c1);
                wmma::mma_sync(c1, al, bh, c1);
            }
        }
        __syncthreads();
    }

    wmma::store_matrix_sync(&out[(size_t)(m0 + wm) * NTP + n0 + wn],      c0, NTP, wmma::mem_row_major);
    wmma::store_matrix_sync(&out[(size_t)(m0 + wm) * NTP + n0 + wn + 16], c1, NTP, wmma::mem_row_major);
}

// ---------------- per-node concat GEMM for tiny layers ----------------------
template<int DIN, int K, int DOUT>
__global__ void __launch_bounds__(256)
k_gemm_node(const float* __restrict__ T, const float* __restrict__ Wb,
            float* __restrict__ out) {
    constexpr int NT = K * DOUT;
    __shared__ float sWt[DIN * NT];
    for (int idx = threadIdx.x; idx < K * DIN * DOUT; idx += blockDim.x) {
        int k = idx / (DIN * DOUT);
        int rem = idx - k * DIN * DOUT;
        int i = rem / DOUT, j = rem - i * DOUT;
        sWt[i * NT + k * DOUT + j] = Wb[idx];
    }
    __syncthreads();
    int n = blockIdx.x * blockDim.x + threadIdx.x;
    if (n >= N_NODES) return;
    float x[DIN];
    #pragma unroll
    for (int i = 0; i < DIN; i++) x[i] = __ldg(&T[(size_t)n * DIN + i]);
    float acc[NT];
    #pragma unroll
    for (int c = 0; c < NT; c++) acc[c] = 0.f;
    #pragma unroll
    for (int i = 0; i < DIN; i++) {
        float xi = x[i];
        #pragma unroll
        for (int c = 0; c < NT; c++) acc[c] += xi * sWt[i * NT + c];
    }
    #pragma unroll
    for (int c = 0; c < NT; c++) out[(size_t)n * NT + c] = acc[c];
}

// ---------------- fused CSR prop + Clenshaw combine + epilogue --------------
// Unrolled x4 edge loop: batch (src,w) loads, then 4 independent gathers (MLP).
template<int LANES, int VEC>
__global__ void __launch_bounds__(256)
k_prop2(const int* __restrict__ rowptr, const int* __restrict__ csrc,
        const float* __restrict__ cw,
        const float* __restrict__ tin, int tin_stride,
        const float* __restrict__ xw, int xw_stride,
        const float* __restrict__ sub, int sub_stride,
        float* __restrict__ outp, float wscale, int mode,
        const float* __restrict__ bias,
        const float* __restrict__ bng, const float* __restrict__ bnb,
        const float* __restrict__ bnm, const float* __restrict__ bnv) {
    long long idx = (long long)blockIdx.x * blockDim.x + threadIdx.x;
    int n = (int)(idx / LANES);
    int l = (int)(idx - (long long)n * LANES);
    if (n >= N_NODES) return;
    int j0 = rowptr[n], j1 = rowptr[n + 1];
    constexpr int DIM = LANES * VEC;
    float acc[VEC];
    #pragma unroll
    for (int v = 0; v < VEC; v++) acc[v] = 0.f;

    int j = j0;
    for (; j + 4 <= j1; j += 4) {
        int   s0 = __ldg(&csrc[j]),   s1 = __ldg(&csrc[j+1]);
        int   s2 = __ldg(&csrc[j+2]), s3 = __ldg(&csrc[j+3]);
        float w0 = __ldg(&cw[j]),     w1 = __ldg(&cw[j+1]);
        float w2 = __ldg(&cw[j+2]),   w3 = __ldg(&cw[j+3]);
        const float* p0 = tin + (size_t)s0 * tin_stride + l * VEC;
        const float* p1 = tin + (size_t)s1 * tin_stride + l * VEC;
        const float* p2 = tin + (size_t)s2 * tin_stride + l * VEC;
        const float* p3 = tin + (size_t)s3 * tin_stride + l * VEC;
        if constexpr (VEC == 4) {
            float4 t0 = *(const float4*)p0;
            float4 t1 = *(const float4*)p1;
            float4 t2 = *(const float4*)p2;
            float4 t3 = *(const float4*)p3;
            acc[0] += w0*t0.x + w1*t1.x + w2*t2.x + w3*t3.x;
            acc[1] += w0*t0.y + w1*t1.y + w2*t2.y + w3*t3.y;
            acc[2] += w0*t0.z + w1*t1.z + w2*t2.z + w3*t3.z;
            acc[3] += w0*t0.w + w1*t1.w + w2*t2.w + w3*t3.w;
        } else if constexpr (VEC == 2) {
            float2 t0 = *(const float2*)p0;
            float2 t1 = *(const float2*)p1;
            float2 t2 = *(const float2*)p2;
            float2 t3 = *(const float2*)p3;
            acc[0] += w0*t0.x + w1*t1.x + w2*t2.x + w3*t3.x;
            acc[1] += w0*t0.y + w1*t1.y + w2*t2.y + w3*t3.y;
        } else {
            float t0 = *p0, t1 = *p1, t2 = *p2, t3 = *p3;
            acc[0] += w0*t0 + w1*t1 + w2*t2 + w3*t3;
        }
    }
    for (; j < j1; j++) {
        int s   = __ldg(&csrc[j]);
        float w = __ldg(&cw[j]);
        const float* tp = tin + (size_t)s * tin_stride + l * VEC;
        #pragma unroll
        for (int v = 0; v < VEC; v++) acc[v] += w * tp[v];
    }

    const float* xp = xw + (size_t)n * xw_stride + l * VEC;
    const float* sp = sub ? sub + (size_t)n * sub_stride + l * VEC : nullptr;
    float* op = outp + (size_t)n * DIM + l * VEC;
    #pragma unroll
    for (int v = 0; v < VEC; v++) {
        float z = xp[v] + wscale * acc[v];
        if (sp) z -= sp[v];
        if (mode >= 1) {
            int jch = l * VEC + v;
            z += bias[jch];
            if (mode == 2) {
                z = (z - bnm[jch]) * (bng[jch] * rsqrtf(bnv[jch] + 1e-5f)) + bnb[jch];
                z = fmaxf(z, 0.f);
            }
        }
        op[v] = z;
    }
}

// ---------------- host-side layer driver (Clenshaw, tensor GEMM) ------------
template<int DIN, int DOUT, int K, int NTP, int LANES, int VEC>
static void cheb_layer(const float* input, const float* Wb, const float* bias,
                       const float* bng, const float* bnb, const float* bnm, const float* bnv,
                       float* out, int final_mode,
                       const int* rowptr, const int* csrc, const float* cw,
                       float* xw, float* r0, float* r1, float* r2,
                       __nv_bfloat16* xhi, __nv_bfloat16* xlo,
                       __nv_bfloat16* whi, __nv_bfloat16* wlo) {
    static_assert(LANES * VEC == DOUT, "bad LANES/VEC");

    if constexpr (DIN >= 64) {
        k_split<DIN><<<(N_NODES * DIN / 4 + 255) / 256, 256>>>(input, xhi, xlo);
        k_wsplit<DIN, K, DOUT, NTP><<<(DIN * NTP + 255) / 256, 256>>>(Wb, whi, wlo);
        dim3 grid((N_NODES + 63) / 64, NTP / 64);
        k_gemm_wmma<DIN, NTP><<<grid, 256>>>(xhi, xlo, whi, wlo, xw);
    } else {
        k_gemm_node<DIN, K, DOUT><<<(N_NODES + 255) / 256, 256>>>(input, Wb, xw);
    }
    constexpr int XWS = (DIN >= 64) ? NTP : K * DOUT;

    long long ptot = (long long)N_NODES * LANES;
    int pgrid = (int)((ptot + 255) / 256);

    const float* b1p = xw + (size_t)(K - 1) * DOUT; int b1s = XWS;
    const float* b2p = nullptr;                     int b2s = 0;
    float* rot[3] = {r0, r1, r2};
    int nx = 0;
    for (int k = K - 2; k >= 1; k--) {
        float* t = rot[nx];
        nx = (nx + 1) % 3;
        k_prop2<LANES, VEC><<<pgrid, 256>>>(rowptr, csrc, cw,
            b1p, b1s, xw + (size_t)k * DOUT, XWS, b2p, b2s,
            t, 2.f, 0, nullptr, nullptr, nullptr, nullptr, nullptr);
        b2p = b1p; b2s = b1s;
        b1p = t;   b1s = DOUT;
    }
    k_prop2<LANES, VEC><<<pgrid, 256>>>(rowptr, csrc, cw,
        b1p, b1s, xw, XWS, b2p, b2s,
        out, 1.f, final_mode, bias, bng, bnb, bnm, bnv);
}

extern "C" void kernel_launch(void* const* d_in, const int* in_sizes, int n_in,
                              void* d_out, int out_size) {
    const float* x   = (const float*)d_in[0];
    const int*   ei  = (const int*)d_in[1];
    const int*   src = ei;
    const int*   dst = ei + N_EDGES;
    const float* W1 = (const float*)d_in[2];  const float* b1 = (const float*)d_in[3];
    const float* W2 = (const float*)d_in[4];  const float* b2 = (const float*)d_in[5];
    const float* W3 = (const float*)d_in[6];  const float* b3 = (const float*)d_in[7];
    const float* W4 = (const float*)d_in[8];  const float* b4 = (const float*)d_in[9];
    const float* bn1g = (const float*)d_in[10]; const float* bn1b = (const float*)d_in[11];
    const float* bn1m = (const float*)d_in[12]; const float* bn1v = (const float*)d_in[13];
    const float* bn2g = (const float*)d_in[14]; const float* bn2b = (const float*)d_in[15];
    const float* bn2m = (const float*)d_in[16]; const float* bn2v = (const float*)d_in[17];
    const float* bn3g = (const float*)d_in[18]; const float* bn3b = (const float*)d_in[19];
    const float* bn3m = (const float*)d_in[20]; const float* bn3v = (const float*)d_in[21];

    int *degi, *rowptr, *cursor, *partial, *csrc;
    float *dinv, *cw, *xw, *bufA, *bufB, *bufC, *h;
    __nv_bfloat16 *xhi, *xlo, *whi, *wlo;
    cudaGetSymbolAddress((void**)&degi,   g_degi);
    cudaGetSymbolAddress((void**)&dinv,   g_dinv);
    cudaGetSymbolAddress((void**)&rowptr, g_rowptr);
    cudaGetSymbolAddress((void**)&cursor, g_cursor);
    cudaGetSymbolAddress((void**)&partial,g_partial);
    cudaGetSymbolAddress((void**)&csrc,   g_csrc);
    cudaGetSymbolAddress((void**)&cw,     g_cw);
    cudaGetSymbolAddress((void**)&xw,     g_xw);
    cudaGetSymbolAddress((void**)&bufA,   g_bufA);
    cudaGetSymbolAddress((void**)&bufB,   g_bufB);
    cudaGetSymbolAddress((void**)&bufC,   g_bufC);
    cudaGetSymbolAddress((void**)&h,      g_h);
    cudaGetSymbolAddress((void**)&xhi,    g_xhi);
    cudaGetSymbolAddress((void**)&xlo,    g_xlo);
    cudaGetSymbolAddress((void**)&whi,    g_whi);
    cudaGetSymbolAddress((void**)&wlo,    g_wlo);

    // ---- CSR build ----
    k_zeroi<<<(N_NODES + 255) / 256, 256>>>(degi, N_NODES);
    k_zeroi<<<(N_NODES + 255) / 256, 256>>>(cursor, N_NODES);
    k_hist  <<<(N_EDGES + 255) / 256, 256>>>(dst, degi);
    k_dinv_k<<<(N_NODES + 255) / 256, 256>>>(degi, dinv);
    k_scan1 <<<NBLK, SCAN_B>>>(degi, rowptr, partial);
    k_scan2 <<<1, 128>>>(partial);
    k_scan3 <<<(N_NODES + 255) / 256, 256>>>(rowptr, partial);
    k_fill  <<<(N_EDGES + 255) / 256, 256>>>(src, dst, dinv, rowptr, cursor, csrc, cw);

    // layer 1: 128 -> 64, K=8, BN+ReLU
    cheb_layer<128, 64, 8, 512, 16, 4>(x, W1, b1, bn1g, bn1b, bn1m, bn1v, h, 2,
                                       rowptr, csrc, cw, xw, bufA, bufB, bufC,
                                       xhi, xlo, whi, wlo);
    // layer 2: 64 -> 18, K=6, BN+ReLU
    cheb_layer<64, 18, 6, 128, 9, 2>(h, W2, b2, bn2g, bn2b, bn2m, bn2v, h, 2,
                                     rowptr, csrc, cw, xw, bufA, bufB, bufC,
                                     xhi, xlo, whi, wlo);
    // layer 3: 18 -> 9, K=4, BN+ReLU
    cheb_layer<18, 9, 4, 0, 9, 1>(h, W3, b3, bn3g, bn3b, bn3m, bn3v, h, 2,
                                  rowptr, csrc, cw, xw, bufA, bufB, bufC,
                                  xhi, xlo, whi, wlo);
    // layer 4: 9 -> 10, K=4, bias only, write d_out
    cheb_layer<9, 10, 4, 0, 5, 2>(h, W4, b4, nullptr, nullptr, nullptr, nullptr,
                                  (float*)d_out, 1,
                                  rowptr, csrc, cw, xw, bufA, bufB, bufC,
                                  xhi, xlo, whi, wlo);
}